// round 5
// baseline (speedup 1.0000x reference)
#include <cuda_runtime.h>

// ---- problem constants ----
#define B_   16
#define S_   512
#define D_   768
#define H_   12
#define DK_  64
#define DFF_ 3072
#define L_   12
#define NC_  100

#define BSD  (B_*S_*D_)            // 6,291,456 floats
#define BSF  (B_*S_*DFF_)          // 12,582,912 floats

// scratch: X, Y, Qb, Kb, Vb, Cb, Ab (7×BSD) + Hb (BSF) + pooled + clf hidden
__device__ __align__(16) float g_scratch[7*(size_t)BSD + (size_t)BSF + B_*D_ + B_*(D_/2)];

// ---------------------------------------------------------------------------
// Embedding + sinusoidal positional encoding
// grid: (B*S, 3) x 256 threads
// ---------------------------------------------------------------------------
__global__ __launch_bounds__(256) void embed_k(const int* __restrict__ ids,
                                               const float* __restrict__ emb,
                                               float* __restrict__ X)
{
    int bs = blockIdx.x;
    int d  = blockIdx.y * 256 + threadIdx.x;
    int s  = bs & (S_ - 1);
    int tok = ids[bs];
    int i2 = (d >> 1) * 2;
    float freq = expf((float)i2 * (-9.210340371976184f / (float)D_)); // -ln(10000)/D
    float ang  = (float)s * freq;
    float pe   = (d & 1) ? cosf(ang) : sinf(ang);
    X[(size_t)bs * D_ + d] = emb[(size_t)tok * D_ + d] + pe;
}

// ---------------------------------------------------------------------------
// Generic SGEMM: C[M,N] = act(A[M,K] @ W[K,N] + bias[N])
// 64x64 tile, BK=16, 256 threads, 4x4 microtile. ACT=1 -> relu.
// Requires K%16==0, N%4==0 (holds for all call sites). M,N edges guarded.
// ---------------------------------------------------------------------------
template<int ACT>
__global__ __launch_bounds__(256) void gemm_k(const float* __restrict__ A,
                                              const float* __restrict__ W,
                                              const float* __restrict__ bias,
                                              float* __restrict__ C,
                                              int M, int N, int K)
{
    __shared__ float As[16][64];
    __shared__ float Ws[16][64];

    const int tid = threadIdx.x;
    const int m0 = blockIdx.y * 64, n0 = blockIdx.x * 64;
    const int ty = tid >> 4, tx = tid & 15;
    const int am = tid >> 2, ak = (tid & 3) * 4;   // A loader: row am, k-offset ak
    const int wk = tid >> 4, wn = (tid & 15) * 4;  // W loader: k-row wk, n-offset wn

    float acc[4][4] = {};
    const bool aval = (m0 + am) < M;

    for (int k0 = 0; k0 < K; k0 += 16) {
        float4 av = make_float4(0.f, 0.f, 0.f, 0.f);
        if (aval) av = *(const float4*)&A[(size_t)(m0 + am) * K + k0 + ak];
        As[ak + 0][am] = av.x; As[ak + 1][am] = av.y;
        As[ak + 2][am] = av.z; As[ak + 3][am] = av.w;

        float4 wv;
        if (n0 + wn + 3 < N) {
            wv = *(const float4*)&W[(size_t)(k0 + wk) * N + n0 + wn];
        } else {
            const float* wr = &W[(size_t)(k0 + wk) * N];
            wv.x = (n0 + wn + 0 < N) ? wr[n0 + wn + 0] : 0.f;
            wv.y = (n0 + wn + 1 < N) ? wr[n0 + wn + 1] : 0.f;
            wv.z = (n0 + wn + 2 < N) ? wr[n0 + wn + 2] : 0.f;
            wv.w = 0.f;
        }
        Ws[wk][wn + 0] = wv.x; Ws[wk][wn + 1] = wv.y;
        Ws[wk][wn + 2] = wv.z; Ws[wk][wn + 3] = wv.w;

        __syncthreads();
        #pragma unroll
        for (int kk = 0; kk < 16; kk++) {
            float4 a = *(const float4*)&As[kk][ty * 4];
            float4 b = *(const float4*)&Ws[kk][tx * 4];
            acc[0][0] += a.x * b.x; acc[0][1] += a.x * b.y; acc[0][2] += a.x * b.z; acc[0][3] += a.x * b.w;
            acc[1][0] += a.y * b.x; acc[1][1] += a.y * b.y; acc[1][2] += a.y * b.z; acc[1][3] += a.y * b.w;
            acc[2][0] += a.z * b.x; acc[2][1] += a.z * b.y; acc[2][2] += a.z * b.z; acc[2][3] += a.z * b.w;
            acc[3][0] += a.w * b.x; acc[3][1] += a.w * b.y; acc[3][2] += a.w * b.z; acc[3][3] += a.w * b.w;
        }
        __syncthreads();
    }

    #pragma unroll
    for (int i = 0; i < 4; i++) {
        int m = m0 + ty * 4 + i;
        if (m >= M) continue;
        #pragma unroll
        for (int j = 0; j < 4; j++) {
            int n = n0 + tx * 4 + j;
            if (n < N) {
                float v = acc[i][j] + bias[n];
                if (ACT) v = fmaxf(v, 0.f);
                C[(size_t)m * N + n] = v;
            }
        }
    }
}

// ---------------------------------------------------------------------------
// Flash-style attention with relative-position bias.
// grid: (S/64, H, B), 256 threads. BQ=64 queries, chunks of 32 keys.
// Q/K/V/O layout: [B, S, H*DK] (head h at column offset h*DK).
// bias(h,i,j) = rb[(j - i + S - 1)*H + h]  (rb already offset to layer l)
// ---------------------------------------------------------------------------
__global__ __launch_bounds__(256) void attn_k(const float* __restrict__ Q,
                                              const float* __restrict__ Km,
                                              const float* __restrict__ V,
                                              const float* __restrict__ rb,
                                              float* __restrict__ O)
{
    const int q0 = blockIdx.x * 64;
    const int h  = blockIdx.y;
    const int b  = blockIdx.z;

    __shared__ float Qs[64][65];
    __shared__ float Kt[64][33];
    __shared__ float Vs[32][68];
    __shared__ float Ss[64][33];
    __shared__ float m_s[64], l_s[64], al_s[64];

    const int tid = threadIdx.x;
    const int ty = tid >> 4, tx = tid & 15;

    // load Q tile (64x64)
    #pragma unroll
    for (int r = 0; r < 4; r++) {
        int lin = tid + r * 256;
        int qr = lin >> 4, dc = (lin & 15) * 4;
        float4 v4 = *(const float4*)&Q[(((size_t)b * S_ + q0 + qr) * D_) + h * DK_ + dc];
        Qs[qr][dc + 0] = v4.x; Qs[qr][dc + 1] = v4.y;
        Qs[qr][dc + 2] = v4.z; Qs[qr][dc + 3] = v4.w;
    }
    if (tid < 64) { m_s[tid] = -1e30f; l_s[tid] = 0.f; }

    float o[4][4];
    #pragma unroll
    for (int i = 0; i < 4; i++)
        #pragma unroll
        for (int j = 0; j < 4; j++) o[i][j] = 0.f;

    __syncthreads();

    for (int j0 = 0; j0 < S_; j0 += 32) {
        // load K chunk transposed, V chunk
        #pragma unroll
        for (int r = 0; r < 2; r++) {
            int lin = tid + r * 256;
            int kr = lin >> 4, dc = (lin & 15) * 4;
            size_t gidx = (((size_t)b * S_ + j0 + kr) * D_) + h * DK_ + dc;
            float4 kv = *(const float4*)&Km[gidx];
            Kt[dc + 0][kr] = kv.x; Kt[dc + 1][kr] = kv.y;
            Kt[dc + 2][kr] = kv.z; Kt[dc + 3][kr] = kv.w;
            *(float4*)&Vs[kr][dc] = *(const float4*)&V[gidx];
        }
        __syncthreads();

        // S tile: each thread computes 4 q-rows x 2 k-cols
        float sa[4][2] = {};
        #pragma unroll 8
        for (int d = 0; d < 64; d++) {
            float b0 = Kt[d][tx * 2 + 0];
            float b1 = Kt[d][tx * 2 + 1];
            #pragma unroll
            for (int i = 0; i < 4; i++) {
                float a = Qs[ty * 4 + i][d];
                sa[i][0] += a * b0;
                sa[i][1] += a * b1;
            }
        }
        #pragma unroll
        for (int i = 0; i < 4; i++) {
            #pragma unroll
            for (int j = 0; j < 2; j++) {
                int qi = ty * 4 + i, kj = tx * 2 + j;
                int r = (j0 + kj) - (q0 + qi) + (S_ - 1);
                Ss[qi][kj] = sa[i][j] * 0.125f + rb[r * H_ + h];
            }
        }
        __syncthreads();

        // online softmax per row (threads 0..63)
        if (tid < 64) {
            float mo = m_s[tid], cm = mo;
            #pragma unroll
            for (int c = 0; c < 32; c++) cm = fmaxf(cm, Ss[tid][c]);
            float al = expf(mo - cm);
            float rs = 0.f;
            #pragma unroll
            for (int c = 0; c < 32; c++) {
                float p = expf(Ss[tid][c] - cm);
                Ss[tid][c] = p;
                rs += p;
            }
            l_s[tid] = l_s[tid] * al + rs;
            m_s[tid] = cm;
            al_s[tid] = al;
        }
        __syncthreads();

        // rescale O, accumulate P @ V
        #pragma unroll
        for (int i = 0; i < 4; i++) {
            float al = al_s[ty * 4 + i];
            o[i][0] *= al; o[i][1] *= al; o[i][2] *= al; o[i][3] *= al;
        }
        #pragma unroll 4
        for (int k = 0; k < 32; k++) {
            float4 vv = *(const float4*)&Vs[k][tx * 4];
            #pragma unroll
            for (int i = 0; i < 4; i++) {
                float p = Ss[ty * 4 + i][k];
                o[i][0] += p * vv.x; o[i][1] += p * vv.y;
                o[i][2] += p * vv.z; o[i][3] += p * vv.w;
            }
        }
        __syncthreads();
    }

    #pragma unroll
    for (int i = 0; i < 4; i++) {
        float inv = 1.f / l_s[ty * 4 + i];
        size_t oidx = (((size_t)b * S_ + q0 + ty * 4 + i) * D_) + h * DK_ + tx * 4;
        O[oidx + 0] = o[i][0] * inv;
        O[oidx + 1] = o[i][1] * inv;
        O[oidx + 2] = o[i][2] * inv;
        O[oidx + 3] = o[i][3] * inv;
    }
}

// ---------------------------------------------------------------------------
// Fused residual-add + LayerNorm: Y = LN(X + R) * g + be. One block per row.
// ---------------------------------------------------------------------------
__global__ __launch_bounds__(256) void ln_k(const float* __restrict__ X,
                                            const float* __restrict__ R,
                                            const float* __restrict__ g,
                                            const float* __restrict__ be,
                                            float* __restrict__ Y)
{
    __shared__ float red[256];
    const int row = blockIdx.x, tid = threadIdx.x;
    const size_t off = (size_t)row * D_;

    float v0 = X[off + tid      ] + R[off + tid      ];
    float v1 = X[off + tid + 256] + R[off + tid + 256];
    float v2 = X[off + tid + 512] + R[off + tid + 512];

    red[tid] = v0 + v1 + v2;
    __syncthreads();
    #pragma unroll
    for (int s = 128; s > 0; s >>= 1) {
        if (tid < s) red[tid] += red[tid + s];
        __syncthreads();
    }
    float mean = red[0] * (1.f / (float)D_);
    __syncthreads();

    float d0 = v0 - mean, d1 = v1 - mean, d2 = v2 - mean;
    red[tid] = d0 * d0 + d1 * d1 + d2 * d2;
    __syncthreads();
    #pragma unroll
    for (int s = 128; s > 0; s >>= 1) {
        if (tid < s) red[tid] += red[tid + s];
        __syncthreads();
    }
    float inv = rsqrtf(red[0] * (1.f / (float)D_) + 1e-5f);

    Y[off + tid      ] = d0 * inv * g[tid      ] + be[tid      ];
    Y[off + tid + 256] = d1 * inv * g[tid + 256] + be[tid + 256];
    Y[off + tid + 512] = d2 * inv * g[tid + 512] + be[tid + 512];
}

// ---------------------------------------------------------------------------
// Mean pooling over sequence: P[b,d] = mean_s X[b,s,d].  grid: (3, B)
// ---------------------------------------------------------------------------
__global__ __launch_bounds__(256) void pool_k(const float* __restrict__ X,
                                              float* __restrict__ P)
{
    int b = blockIdx.y;
    int d = blockIdx.x * 256 + threadIdx.x;
    float s = 0.f;
    for (int sq = 0; sq < S_; sq++)
        s += X[(((size_t)b * S_) + sq) * D_ + d];
    P[(size_t)b * D_ + d] = s * (1.f / (float)S_);
}

// ---------------------------------------------------------------------------
extern "C" void kernel_launch(void* const* d_in, const int* in_sizes, int n_in,
                              void* d_out, int out_size)
{
    (void)in_sizes; (void)n_in; (void)out_size;

    const int*   ids = (const int*)  d_in[0];
    const float* emb = (const float*)d_in[1];
    const float* wq  = (const float*)d_in[2];
    const float* bq  = (const float*)d_in[3];
    const float* wk  = (const float*)d_in[4];
    const float* bk  = (const float*)d_in[5];
    const float* wv  = (const float*)d_in[6];
    const float* bv  = (const float*)d_in[7];
    const float* wo  = (const float*)d_in[8];
    const float* bo  = (const float*)d_in[9];
    const float* rb  = (const float*)d_in[10];
    const float* w1  = (const float*)d_in[11];
    const float* b1  = (const float*)d_in[12];
    const float* w2  = (const float*)d_in[13];
    const float* b2  = (const float*)d_in[14];
    const float* g1  = (const float*)d_in[15];
    const float* be1 = (const float*)d_in[16];
    const float* g2  = (const float*)d_in[17];
    const float* be2 = (const float*)d_in[18];
    const float* cw1 = (const float*)d_in[19];
    const float* cb1 = (const float*)d_in[20];
    const float* cw2 = (const float*)d_in[21];
    const float* cb2 = (const float*)d_in[22];
    float* out = (float*)d_out;

    float* base = nullptr;
    cudaGetSymbolAddress((void**)&base, g_scratch);

    float* X  = base;
    float* Y  = base + 1 * (size_t)BSD;
    float* Qb = base + 2 * (size_t)BSD;
    float* Kb = base + 3 * (size_t)BSD;
    float* Vb = base + 4 * (size_t)BSD;
    float* Cb = base + 5 * (size_t)BSD;
    float* Ab = base + 6 * (size_t)BSD;
    float* Hb = base + 7 * (size_t)BSD;
    float* Pp = Hb + (size_t)BSF;
    float* Ch = Pp + B_ * D_;

    embed_k<<<dim3(B_ * S_, 3), 256>>>(ids, emb, X);

    const int M = B_ * S_;                 // 8192
    dim3 gProj(D_ / 64,  M / 64);          // (12, 128)
    dim3 gF1  (DFF_ / 64, M / 64);         // (48, 128)

    for (int l = 0; l < L_; l++) {
        size_t oDD = (size_t)l * D_ * D_;
        gemm_k<0><<<gProj, 256>>>(X,  wq + oDD, bq + l * D_, Qb, M, D_, D_);
        gemm_k<0><<<gProj, 256>>>(X,  wk + oDD, bk + l * D_, Kb, M, D_, D_);
        gemm_k<0><<<gProj, 256>>>(X,  wv + oDD, bv + l * D_, Vb, M, D_, D_);
        attn_k<<<dim3(S_ / 64, H_, B_), 256>>>(Qb, Kb, Vb,
                                               rb + (size_t)l * (2 * S_ - 1) * H_, Cb);
        gemm_k<0><<<gProj, 256>>>(Cb, wo + oDD, bo + l * D_, Ab, M, D_, D_);
        ln_k<<<M, 256>>>(X, Ab, g1 + l * D_, be1 + l * D_, Y);
        gemm_k<1><<<gF1, 256>>>(Y, w1 + (size_t)l * D_ * DFF_, b1 + l * DFF_, Hb, M, DFF_, D_);
        gemm_k<0><<<gProj, 256>>>(Hb, w2 + (size_t)l * DFF_ * D_, b2 + l * D_, Ab, M, D_, DFF_);
        ln_k<<<M, 256>>>(Y, Ab, g2 + l * D_, be2 + l * D_, X);
    }

    pool_k<<<dim3(3, B_), 256>>>(X, Pp);
    gemm_k<1><<<dim3(6, 1), 256>>>(Pp, cw1, cb1, Ch, B_, D_ / 2, D_);
    gemm_k<0><<<dim3(2, 1), 256>>>(Ch, cw2, cb2, out, B_, NC_, D_ / 2);
}

// round 8
// speedup vs baseline: 2.0257x; 2.0257x over previous
#include <cuda_runtime.h>

// ---- problem constants ----
#define B_   16
#define S_   512
#define D_   768
#define H_   12
#define DK_  64
#define DFF_ 3072
#define L_   12
#define NC_  100

#define BSD  (B_*S_*D_)            // 6,291,456 floats
#define BSF  (B_*S_*DFF_)          // 12,582,912 floats

__device__ __align__(16) float g_scratch[7*(size_t)BSD + (size_t)BSF + B_*D_ + B_*(D_/2)];

__device__ __forceinline__ float tf32r(float x) {
    unsigned u;
    asm("cvt.rna.tf32.f32 %0, %1;" : "=r"(u) : "f"(x));
    return __uint_as_float(u);
}

// ---------------------------------------------------------------------------
// Embedding + sinusoidal positional encoding
// ---------------------------------------------------------------------------
__global__ __launch_bounds__(256) void embed_k(const int* __restrict__ ids,
                                               const float* __restrict__ emb,
                                               float* __restrict__ X)
{
    int bs = blockIdx.x;
    int d  = blockIdx.y * 256 + threadIdx.x;
    int s  = bs & (S_ - 1);
    int tok = ids[bs];
    int i2 = (d >> 1) * 2;
    float freq = expf((float)i2 * (-9.210340371976184f / (float)D_));
    float ang  = (float)s * freq;
    float pe   = (d & 1) ? cosf(ang) : sinf(ang);
    X[(size_t)bs * D_ + d] = emb[(size_t)tok * D_ + d] + pe;
}

// ---------------------------------------------------------------------------
// TF32 tensor-core GEMM: C[M,N] = act(A[M,K] @ W[K,N] + bias[N])
// Block tile 128x128, BK=16, 256 threads = 8 warps (2 m x 4 n),
// warp tile 64x32 built from mma.sync.m16n8k8 (4 m-tiles x 4 n-tiles).
// Requires M%128==0, N%128==0, K%16==0 (holds for all large call sites).
// ---------------------------------------------------------------------------
template<int ACT>
__global__ __launch_bounds__(256, 2) void gemm_tc(const float* __restrict__ A,
                                                  const float* __restrict__ W,
                                                  const float* __restrict__ bias,
                                                  float* __restrict__ C,
                                                  int M, int N, int K)
{
    __shared__ float As[128][20];   // [m][k] tf32-rounded  (stride 20: frag loads conflict-free)
    __shared__ float Bs[128][20];   // [n][k] tf32-rounded

    const int tid  = threadIdx.x;
    const int m0   = blockIdx.y * 128;
    const int n0   = blockIdx.x * 128;
    const int warp = tid >> 5, lane = tid & 31;
    const int wm   = (warp >> 2) * 64;    // 0 or 64
    const int wn   = (warp & 3) * 32;     // 0,32,64,96
    const int g    = lane >> 2;           // groupID 0..7
    const int tg   = lane & 3;            // thread-in-group 0..3

    float acc[4][4][4];
    #pragma unroll
    for (int i = 0; i < 4; i++)
        #pragma unroll
        for (int j = 0; j < 4; j++)
            #pragma unroll
            for (int r = 0; r < 4; r++) acc[i][j][r] = 0.f;

    const int arow = tid >> 1;            // 0..127
    const int akq  = (tid & 1) * 8;       // 0 or 8

    for (int k0 = 0; k0 < K; k0 += 16) {
        // --- fill A tile: 128x16, 8 consecutive floats per thread ---
        {
            const float* ap = &A[(size_t)(m0 + arow) * K + k0 + akq];
            float4 v0 = *(const float4*)ap;
            float4 v1 = *(const float4*)(ap + 4);
            As[arow][akq + 0] = tf32r(v0.x); As[arow][akq + 1] = tf32r(v0.y);
            As[arow][akq + 2] = tf32r(v0.z); As[arow][akq + 3] = tf32r(v0.w);
            As[arow][akq + 4] = tf32r(v1.x); As[arow][akq + 5] = tf32r(v1.y);
            As[arow][akq + 6] = tf32r(v1.z); As[arow][akq + 7] = tf32r(v1.w);
        }
        // --- fill B tile n-major: Bs[n][k] = W[k0+k][n0+n] ---
        {
            const int nrow = arow;
            #pragma unroll
            for (int i = 0; i < 8; i++) {
                Bs[nrow][akq + i] = tf32r(W[(size_t)(k0 + akq + i) * N + n0 + nrow]);
            }
        }
        __syncthreads();

        #pragma unroll
        for (int kk = 0; kk < 16; kk += 8) {
            unsigned a[4][4], b[4][2];
            #pragma unroll
            for (int mt = 0; mt < 4; mt++) {
                int r = wm + mt * 16 + g;
                a[mt][0] = __float_as_uint(As[r    ][kk + tg    ]);
                a[mt][1] = __float_as_uint(As[r + 8][kk + tg    ]);
                a[mt][2] = __float_as_uint(As[r    ][kk + tg + 4]);
                a[mt][3] = __float_as_uint(As[r + 8][kk + tg + 4]);
            }
            #pragma unroll
            for (int nt = 0; nt < 4; nt++) {
                int c = wn + nt * 8 + g;
                b[nt][0] = __float_as_uint(Bs[c][kk + tg    ]);
                b[nt][1] = __float_as_uint(Bs[c][kk + tg + 4]);
            }
            #pragma unroll
            for (int mt = 0; mt < 4; mt++) {
                #pragma unroll
                for (int nt = 0; nt < 4; nt++) {
                    asm volatile(
                        "mma.sync.aligned.m16n8k8.row.col.f32.tf32.tf32.f32 "
                        "{%0,%1,%2,%3}, {%4,%5,%6,%7}, {%8,%9}, {%0,%1,%2,%3};\n"
                        : "+f"(acc[mt][nt][0]), "+f"(acc[mt][nt][1]),
                          "+f"(acc[mt][nt][2]), "+f"(acc[mt][nt][3])
                        : "r"(a[mt][0]), "r"(a[mt][1]), "r"(a[mt][2]), "r"(a[mt][3]),
                          "r"(b[nt][0]), "r"(b[nt][1]));
                }
            }
        }
        __syncthreads();
    }

    // --- epilogue: bias (+relu), float2 stores ---
    #pragma unroll
    for (int mt = 0; mt < 4; mt++) {
        int r0 = m0 + wm + mt * 16 + g;
        #pragma unroll
        for (int nt = 0; nt < 4; nt++) {
            int cb = n0 + wn + nt * 8 + tg * 2;
            float b0 = bias[cb], b1 = bias[cb + 1];
            float v0 = acc[mt][nt][0] + b0;
            float v1 = acc[mt][nt][1] + b1;
            float v2 = acc[mt][nt][2] + b0;
            float v3 = acc[mt][nt][3] + b1;
            if (ACT) {
                v0 = fmaxf(v0, 0.f); v1 = fmaxf(v1, 0.f);
                v2 = fmaxf(v2, 0.f); v3 = fmaxf(v3, 0.f);
            }
            *(float2*)&C[(size_t)r0 * N + cb]       = make_float2(v0, v1);
            *(float2*)&C[(size_t)(r0 + 8) * N + cb] = make_float2(v2, v3);
        }
    }
}

// ---------------------------------------------------------------------------
// Small fp32 GEMM (classifier only): 64x64 tile, edge-guarded.
// ---------------------------------------------------------------------------
template<int ACT>
__global__ __launch_bounds__(256) void gemm_k(const float* __restrict__ A,
                                              const float* __restrict__ W,
                                              const float* __restrict__ bias,
                                              float* __restrict__ C,
                                              int M, int N, int K)
{
    __shared__ float As[16][64];
    __shared__ float Ws[16][64];

    const int tid = threadIdx.x;
    const int m0 = blockIdx.y * 64, n0 = blockIdx.x * 64;
    const int ty = tid >> 4, tx = tid & 15;
    const int am = tid >> 2, ak = (tid & 3) * 4;
    const int wk = tid >> 4, wn = (tid & 15) * 4;

    float acc[4][4] = {};
    const bool aval = (m0 + am) < M;

    for (int k0 = 0; k0 < K; k0 += 16) {
        float4 av = make_float4(0.f, 0.f, 0.f, 0.f);
        if (aval) av = *(const float4*)&A[(size_t)(m0 + am) * K + k0 + ak];
        As[ak + 0][am] = av.x; As[ak + 1][am] = av.y;
        As[ak + 2][am] = av.z; As[ak + 3][am] = av.w;

        float4 wv;
        if (n0 + wn + 3 < N) {
            wv = *(const float4*)&W[(size_t)(k0 + wk) * N + n0 + wn];
        } else {
            const float* wr = &W[(size_t)(k0 + wk) * N];
            wv.x = (n0 + wn + 0 < N) ? wr[n0 + wn + 0] : 0.f;
            wv.y = (n0 + wn + 1 < N) ? wr[n0 + wn + 1] : 0.f;
            wv.z = (n0 + wn + 2 < N) ? wr[n0 + wn + 2] : 0.f;
            wv.w = 0.f;
        }
        Ws[wk][wn + 0] = wv.x; Ws[wk][wn + 1] = wv.y;
        Ws[wk][wn + 2] = wv.z; Ws[wk][wn + 3] = wv.w;

        __syncthreads();
        #pragma unroll
        for (int kk = 0; kk < 16; kk++) {
            float4 a = *(const float4*)&As[kk][ty * 4];
            float4 b = *(const float4*)&Ws[kk][tx * 4];
            acc[0][0] += a.x * b.x; acc[0][1] += a.x * b.y; acc[0][2] += a.x * b.z; acc[0][3] += a.x * b.w;
            acc[1][0] += a.y * b.x; acc[1][1] += a.y * b.y; acc[1][2] += a.y * b.z; acc[1][3] += a.y * b.w;
            acc[2][0] += a.z * b.x; acc[2][1] += a.z * b.y; acc[2][2] += a.z * b.z; acc[2][3] += a.z * b.w;
            acc[3][0] += a.w * b.x; acc[3][1] += a.w * b.y; acc[3][2] += a.w * b.z; acc[3][3] += a.w * b.w;
        }
        __syncthreads();
    }

    #pragma unroll
    for (int i = 0; i < 4; i++) {
        int m = m0 + ty * 4 + i;
        if (m >= M) continue;
        #pragma unroll
        for (int j = 0; j < 4; j++) {
            int n = n0 + tx * 4 + j;
            if (n < N) {
                float v = acc[i][j] + bias[n];
                if (ACT) v = fmaxf(v, 0.f);
                C[(size_t)m * N + n] = v;
            }
        }
    }
}

// ---------------------------------------------------------------------------
// Flash-style attention with relative-position bias (unchanged this round).
// ---------------------------------------------------------------------------
__global__ __launch_bounds__(256) void attn_k(const float* __restrict__ Q,
                                              const float* __restrict__ Km,
                                              const float* __restrict__ V,
                                              const float* __restrict__ rb,
                                              float* __restrict__ O)
{
    const int q0 = blockIdx.x * 64;
    const int h  = blockIdx.y;
    const int b  = blockIdx.z;

    __shared__ float Qs[64][65];
    __shared__ float Kt[64][33];
    __shared__ float Vs[32][68];
    __shared__ float Ss[64][33];
    __shared__ float m_s[64], l_s[64], al_s[64];

    const int tid = threadIdx.x;
    const int ty = tid >> 4, tx = tid & 15;

    #pragma unroll
    for (int r = 0; r < 4; r++) {
        int lin = tid + r * 256;
        int qr = lin >> 4, dc = (lin & 15) * 4;
        float4 v4 = *(const float4*)&Q[(((size_t)b * S_ + q0 + qr) * D_) + h * DK_ + dc];
        Qs[qr][dc + 0] = v4.x; Qs[qr][dc + 1] = v4.y;
        Qs[qr][dc + 2] = v4.z; Qs[qr][dc + 3] = v4.w;
    }
    if (tid < 64) { m_s[tid] = -1e30f; l_s[tid] = 0.f; }

    float o[4][4];
    #pragma unroll
    for (int i = 0; i < 4; i++)
        #pragma unroll
        for (int j = 0; j < 4; j++) o[i][j] = 0.f;

    __syncthreads();

    for (int j0 = 0; j0 < S_; j0 += 32) {
        #pragma unroll
        for (int r = 0; r < 2; r++) {
            int lin = tid + r * 256;
            int kr = lin >> 4, dc = (lin & 15) * 4;
            size_t gidx = (((size_t)b * S_ + j0 + kr) * D_) + h * DK_ + dc;
            float4 kv = *(const float4*)&Km[gidx];
            Kt[dc + 0][kr] = kv.x; Kt[dc + 1][kr] = kv.y;
            Kt[dc + 2][kr] = kv.z; Kt[dc + 3][kr] = kv.w;
            *(float4*)&Vs[kr][dc] = *(const float4*)&V[gidx];
        }
        __syncthreads();

        float sa[4][2] = {};
        #pragma unroll 8
        for (int d = 0; d < 64; d++) {
            float b0 = Kt[d][tx * 2 + 0];
            float b1 = Kt[d][tx * 2 + 1];
            #pragma unroll
            for (int i = 0; i < 4; i++) {
                float a = Qs[ty * 4 + i][d];
                sa[i][0] += a * b0;
                sa[i][1] += a * b1;
            }
        }
        #pragma unroll
        for (int i = 0; i < 4; i++) {
            #pragma unroll
            for (int j = 0; j < 2; j++) {
                int qi = ty * 4 + i, kj = tx * 2 + j;
                int r = (j0 + kj) - (q0 + qi) + (S_ - 1);
                Ss[qi][kj] = sa[i][j] * 0.125f + rb[r * H_ + h];
            }
        }
        __syncthreads();

        if (tid < 64) {
            float mo = m_s[tid], cm = mo;
            #pragma unroll
            for (int c = 0; c < 32; c++) cm = fmaxf(cm, Ss[tid][c]);
            float al = expf(mo - cm);
            float rs = 0.f;
            #pragma unroll
            for (int c = 0; c < 32; c++) {
                float p = expf(Ss[tid][c] - cm);
                Ss[tid][c] = p;
                rs += p;
            }
            l_s[tid] = l_s[tid] * al + rs;
            m_s[tid] = cm;
            al_s[tid] = al;
        }
        __syncthreads();

        #pragma unroll
        for (int i = 0; i < 4; i++) {
            float al = al_s[ty * 4 + i];
            o[i][0] *= al; o[i][1] *= al; o[i][2] *= al; o[i][3] *= al;
        }
        #pragma unroll 4
        for (int k = 0; k < 32; k++) {
            float4 vv = *(const float4*)&Vs[k][tx * 4];
            #pragma unroll
            for (int i = 0; i < 4; i++) {
                float p = Ss[ty * 4 + i][k];
                o[i][0] += p * vv.x; o[i][1] += p * vv.y;
                o[i][2] += p * vv.z; o[i][3] += p * vv.w;
            }
        }
        __syncthreads();
    }

    #pragma unroll
    for (int i = 0; i < 4; i++) {
        float inv = 1.f / l_s[ty * 4 + i];
        size_t oidx = (((size_t)b * S_ + q0 + ty * 4 + i) * D_) + h * DK_ + tx * 4;
        O[oidx + 0] = o[i][0] * inv;
        O[oidx + 1] = o[i][1] * inv;
        O[oidx + 2] = o[i][2] * inv;
        O[oidx + 3] = o[i][3] * inv;
    }
}

// ---------------------------------------------------------------------------
// Fused residual-add + LayerNorm
// ---------------------------------------------------------------------------
__global__ __launch_bounds__(256) void ln_k(const float* __restrict__ X,
                                            const float* __restrict__ R,
                                            const float* __restrict__ g,
                                            const float* __restrict__ be,
                                            float* __restrict__ Y)
{
    __shared__ float red[256];
    const int row = blockIdx.x, tid = threadIdx.x;
    const size_t off = (size_t)row * D_;

    float v0 = X[off + tid      ] + R[off + tid      ];
    float v1 = X[off + tid + 256] + R[off + tid + 256];
    float v2 = X[off + tid + 512] + R[off + tid + 512];

    red[tid] = v0 + v1 + v2;
    __syncthreads();
    #pragma unroll
    for (int s = 128; s > 0; s >>= 1) {
        if (tid < s) red[tid] += red[tid + s];
        __syncthreads();
    }
    float mean = red[0] * (1.f / (float)D_);
    __syncthreads();

    float d0 = v0 - mean, d1 = v1 - mean, d2 = v2 - mean;
    red[tid] = d0 * d0 + d1 * d1 + d2 * d2;
    __syncthreads();
    #pragma unroll
    for (int s = 128; s > 0; s >>= 1) {
        if (tid < s) red[tid] += red[tid + s];
        __syncthreads();
    }
    float inv = rsqrtf(red[0] * (1.f / (float)D_) + 1e-5f);

    Y[off + tid      ] = d0 * inv * g[tid      ] + be[tid      ];
    Y[off + tid + 256] = d1 * inv * g[tid + 256] + be[tid + 256];
    Y[off + tid + 512] = d2 * inv * g[tid + 512] + be[tid + 512];
}

// ---------------------------------------------------------------------------
// Mean pooling over sequence
// ---------------------------------------------------------------------------
__global__ __launch_bounds__(256) void pool_k(const float* __restrict__ X,
                                              float* __restrict__ P)
{
    int b = blockIdx.y;
    int d = blockIdx.x * 256 + threadIdx.x;
    float s = 0.f;
    for (int sq = 0; sq < S_; sq++)
        s += X[(((size_t)b * S_) + sq) * D_ + d];
    P[(size_t)b * D_ + d] = s * (1.f / (float)S_);
}

// ---------------------------------------------------------------------------
extern "C" void kernel_launch(void* const* d_in, const int* in_sizes, int n_in,
                              void* d_out, int out_size)
{
    (void)in_sizes; (void)n_in; (void)out_size;

    const int*   ids = (const int*)  d_in[0];
    const float* emb = (const float*)d_in[1];
    const float* wq  = (const float*)d_in[2];
    const float* bq  = (const float*)d_in[3];
    const float* wk  = (const float*)d_in[4];
    const float* bk  = (const float*)d_in[5];
    const float* wv  = (const float*)d_in[6];
    const float* bv  = (const float*)d_in[7];
    const float* wo  = (const float*)d_in[8];
    const float* bo  = (const float*)d_in[9];
    const float* rb  = (const float*)d_in[10];
    const float* w1  = (const float*)d_in[11];
    const float* b1  = (const float*)d_in[12];
    const float* w2  = (const float*)d_in[13];
    const float* b2  = (const float*)d_in[14];
    const float* g1  = (const float*)d_in[15];
    const float* be1 = (const float*)d_in[16];
    const float* g2  = (const float*)d_in[17];
    const float* be2 = (const float*)d_in[18];
    const float* cw1 = (const float*)d_in[19];
    const float* cb1 = (const float*)d_in[20];
    const float* cw2 = (const float*)d_in[21];
    const float* cb2 = (const float*)d_in[22];
    float* out = (float*)d_out;

    float* base = nullptr;
    cudaGetSymbolAddress((void**)&base, g_scratch);

    float* X  = base;
    float* Y  = base + 1 * (size_t)BSD;
    float* Qb = base + 2 * (size_t)BSD;
    float* Kb = base + 3 * (size_t)BSD;
    float* Vb = base + 4 * (size_t)BSD;
    float* Cb = base + 5 * (size_t)BSD;
    float* Ab = base + 6 * (size_t)BSD;
    float* Hb = base + 7 * (size_t)BSD;
    float* Pp = Hb + (size_t)BSF;
    float* Ch = Pp + B_ * D_;

    embed_k<<<dim3(B_ * S_, 3), 256>>>(ids, emb, X);

    const int M = B_ * S_;                   // 8192
    dim3 gProj(D_ / 128,  M / 128);          // (6, 64)
    dim3 gF1  (DFF_ / 128, M / 128);         // (24, 64)

    for (int l = 0; l < L_; l++) {
        size_t oDD = (size_t)l * D_ * D_;
        gemm_tc<0><<<gProj, 256>>>(X,  wq + oDD, bq + l * D_, Qb, M, D_, D_);
        gemm_tc<0><<<gProj, 256>>>(X,  wk + oDD, bk + l * D_, Kb, M, D_, D_);
        gemm_tc<0><<<gProj, 256>>>(X,  wv + oDD, bv + l * D_, Vb, M, D_, D_);
        attn_k<<<dim3(S_ / 64, H_, B_), 256>>>(Qb, Kb, Vb,
                                               rb + (size_t)l * (2 * S_ - 1) * H_, Cb);
        gemm_tc<0><<<gProj, 256>>>(Cb, wo + oDD, bo + l * D_, Ab, M, D_, D_);
        ln_k<<<M, 256>>>(X, Ab, g1 + l * D_, be1 + l * D_, Y);
        gemm_tc<1><<<gF1, 256>>>(Y, w1 + (size_t)l * D_ * DFF_, b1 + l * DFF_, Hb, M, DFF_, D_);
        gemm_tc<0><<<gProj, 256>>>(Hb, w2 + (size_t)l * DFF_ * D_, b2 + l * D_, Ab, M, D_, DFF_);
        ln_k<<<M, 256>>>(Y, Ab, g2 + l * D_, be2 + l * D_, X);
    }

    pool_k<<<dim3(3, B_), 256>>>(X, Pp);
    gemm_k<1><<<dim3(6, 1), 256>>>(Pp, cw1, cb1, Ch, B_, D_ / 2, D_);
    gemm_k<0><<<dim3(2, 1), 256>>>(Ch, cw2, cb2, out, B_, NC_, D_ / 2);
}

// round 9
// speedup vs baseline: 3.1916x; 1.5755x over previous
#include <cuda_runtime.h>

// ---- problem constants ----
#define B_   16
#define S_   512
#define D_   768
#define H_   12
#define DK_  64
#define DFF_ 3072
#define L_   12
#define NC_  100

#define BSD  (B_*S_*D_)
#define BSF  (B_*S_*DFF_)

__device__ __align__(16) float g_scratch[7*(size_t)BSD + (size_t)BSF + B_*D_ + B_*(D_/2)];

__device__ __forceinline__ unsigned tf32u(float x) {
    unsigned u;
    asm("cvt.rna.tf32.f32 %0, %1;" : "=r"(u) : "f"(x));
    return u;
}

__device__ __forceinline__ void cpa16(void* dst, const void* src) {
    unsigned d = (unsigned)__cvta_generic_to_shared(dst);
    asm volatile("cp.async.cg.shared.global [%0], [%1], 16;\n" :: "r"(d), "l"(src));
}

#define CP_COMMIT() asm volatile("cp.async.commit_group;\n" ::: "memory")
#define CP_WAIT0()  asm volatile("cp.async.wait_group 0;\n" ::: "memory")

#define MMA_TF32(d, a0,a1,a2,a3, b0,b1) \
    asm volatile("mma.sync.aligned.m16n8k8.row.col.f32.tf32.tf32.f32 " \
                 "{%0,%1,%2,%3}, {%4,%5,%6,%7}, {%8,%9}, {%0,%1,%2,%3};\n" \
      : "+f"((d)[0]), "+f"((d)[1]), "+f"((d)[2]), "+f"((d)[3]) \
      : "r"(a0), "r"(a1), "r"(a2), "r"(a3), "r"(b0), "r"(b1))

// ---------------------------------------------------------------------------
// Embedding + sinusoidal positional encoding
// ---------------------------------------------------------------------------
__global__ __launch_bounds__(256) void embed_k(const int* __restrict__ ids,
                                               const float* __restrict__ emb,
                                               float* __restrict__ X)
{
    int bs = blockIdx.x;
    int d  = blockIdx.y * 256 + threadIdx.x;
    int s  = bs & (S_ - 1);
    int tok = ids[bs];
    int i2 = (d >> 1) * 2;
    float freq = expf((float)i2 * (-9.210340371976184f / (float)D_));
    float ang  = (float)s * freq;
    float pe   = (d & 1) ? cosf(ang) : sinf(ang);
    X[(size_t)bs * D_ + d] = emb[(size_t)tok * D_ + d] + pe;
}

// ---------------------------------------------------------------------------
// TF32 tensor-core GEMM core: C[m0:+128, n0:+128] = act(A @ W + bias)
// 128x128 block tile, BK=16, 2-stage cp.async double buffering.
// 256 threads = 8 warps (2m x 4n), warp tile 64x32, mma.m16n8k8.
// Requires rows M multiple of 128 at call site, N%128==0, K%16==0.
// ---------------------------------------------------------------------------
template<int ACT>
__device__ __forceinline__ void gemm_core(const float* __restrict__ A,
                                          const float* __restrict__ W,
                                          const float* __restrict__ bias,
                                          float* __restrict__ C,
                                          int N, int K, int m0, int n0)
{
    __shared__ __align__(16) float As[2][128][20];   // [m][k], row stride 20: frag LDS conflict-free
    __shared__ __align__(16) float Bs[2][16][136];   // [k][n], row stride 136: frag LDS conflict-free

    const int tid  = threadIdx.x;
    const int warp = tid >> 5, lane = tid & 31;
    const int wm   = (warp >> 2) * 64;
    const int wn   = (warp & 3) * 32;
    const int g    = lane >> 2;
    const int tg   = lane & 3;

    float acc[4][4][4];
    #pragma unroll
    for (int i = 0; i < 4; i++)
        #pragma unroll
        for (int j = 0; j < 4; j++)
            #pragma unroll
            for (int r = 0; r < 4; r++) acc[i][j][r] = 0.f;

    // loader chunk indices (two 16B chunks per thread per tile)
    const int cA0 = tid, cA1 = tid + 256;
    const int am0 = cA0 >> 2, ak0 = (cA0 & 3) * 4;
    const int am1 = cA1 >> 2, ak1 = (cA1 & 3) * 4;
    const int bk0 = cA0 >> 5, bn0 = (cA0 & 31) * 4;
    const int bk1 = cA1 >> 5, bn1 = (cA1 & 31) * 4;

    // prologue: stage 0
    cpa16(&As[0][am0][ak0], &A[(size_t)(m0 + am0) * K + ak0]);
    cpa16(&As[0][am1][ak1], &A[(size_t)(m0 + am1) * K + ak1]);
    cpa16(&Bs[0][bk0][bn0], &W[(size_t)bk0 * N + n0 + bn0]);
    cpa16(&Bs[0][bk1][bn1], &W[(size_t)bk1 * N + n0 + bn1]);
    CP_COMMIT();

    const int nk = K >> 4;
    for (int it = 0; it < nk; it++) {
        CP_WAIT0();
        __syncthreads();
        if (it + 1 < nk) {
            const int k0 = (it + 1) << 4;
            const int st = (it + 1) & 1;
            cpa16(&As[st][am0][ak0], &A[(size_t)(m0 + am0) * K + k0 + ak0]);
            cpa16(&As[st][am1][ak1], &A[(size_t)(m0 + am1) * K + k0 + ak1]);
            cpa16(&Bs[st][bk0][bn0], &W[(size_t)(k0 + bk0) * N + n0 + bn0]);
            cpa16(&Bs[st][bk1][bn1], &W[(size_t)(k0 + bk1) * N + n0 + bn1]);
            CP_COMMIT();
        }
        const int st = it & 1;
        #pragma unroll
        for (int kk = 0; kk < 16; kk += 8) {
            unsigned a[4][4], b[4][2];
            #pragma unroll
            for (int mt = 0; mt < 4; mt++) {
                int r = wm + mt * 16 + g;
                a[mt][0] = tf32u(As[st][r    ][kk + tg    ]);
                a[mt][1] = tf32u(As[st][r + 8][kk + tg    ]);
                a[mt][2] = tf32u(As[st][r    ][kk + tg + 4]);
                a[mt][3] = tf32u(As[st][r + 8][kk + tg + 4]);
            }
            #pragma unroll
            for (int nt = 0; nt < 4; nt++) {
                int c = wn + nt * 8 + g;
                b[nt][0] = tf32u(Bs[st][kk + tg    ][c]);
                b[nt][1] = tf32u(Bs[st][kk + tg + 4][c]);
            }
            #pragma unroll
            for (int mt = 0; mt < 4; mt++)
                #pragma unroll
                for (int nt = 0; nt < 4; nt++)
                    MMA_TF32(acc[mt][nt], a[mt][0], a[mt][1], a[mt][2], a[mt][3],
                             b[nt][0], b[nt][1]);
        }
    }

    #pragma unroll
    for (int mt = 0; mt < 4; mt++) {
        int r0 = m0 + wm + mt * 16 + g;
        #pragma unroll
        for (int nt = 0; nt < 4; nt++) {
            int cb = n0 + wn + nt * 8 + tg * 2;
            float b0 = bias[cb], b1 = bias[cb + 1];
            float v0 = acc[mt][nt][0] + b0;
            float v1 = acc[mt][nt][1] + b1;
            float v2 = acc[mt][nt][2] + b0;
            float v3 = acc[mt][nt][3] + b1;
            if (ACT) {
                v0 = fmaxf(v0, 0.f); v1 = fmaxf(v1, 0.f);
                v2 = fmaxf(v2, 0.f); v3 = fmaxf(v3, 0.f);
            }
            *(float2*)&C[(size_t)r0 * N + cb]       = make_float2(v0, v1);
            *(float2*)&C[(size_t)(r0 + 8) * N + cb] = make_float2(v2, v3);
        }
    }
}

template<int ACT>
__global__ __launch_bounds__(256, 2) void gemm_tc(const float* __restrict__ A,
                                                  const float* __restrict__ W,
                                                  const float* __restrict__ bias,
                                                  float* __restrict__ C,
                                                  int N, int K)
{
    gemm_core<ACT>(A, W, bias, C, N, K, blockIdx.y * 128, blockIdx.x * 128);
}

// Fused QKV: grid.x = 18 (which = bx/6, n0 = (bx%6)*128)
__global__ __launch_bounds__(256, 2) void gemm_qkv(const float* __restrict__ X,
                                                   const float* __restrict__ wq,
                                                   const float* __restrict__ wk,
                                                   const float* __restrict__ wv,
                                                   const float* __restrict__ bq,
                                                   const float* __restrict__ bk,
                                                   const float* __restrict__ bv,
                                                   float* __restrict__ Qb,
                                                   float* __restrict__ Kb,
                                                   float* __restrict__ Vb)
{
    const int which = blockIdx.x / 6;
    const int n0 = (blockIdx.x % 6) * 128;
    const float* W  = (which == 0) ? wq : (which == 1) ? wk : wv;
    const float* bi = (which == 0) ? bq : (which == 1) ? bk : bv;
    float*       C  = (which == 0) ? Qb : (which == 1) ? Kb : Vb;
    gemm_core<0>(X, W, bi, C, D_, D_, blockIdx.y * 128, n0);
}

// ---------------------------------------------------------------------------
// Small fp32 GEMM (classifier only)
// ---------------------------------------------------------------------------
template<int ACT>
__global__ __launch_bounds__(256) void gemm_k(const float* __restrict__ A,
                                              const float* __restrict__ W,
                                              const float* __restrict__ bias,
                                              float* __restrict__ C,
                                              int M, int N, int K)
{
    __shared__ float As[16][64];
    __shared__ float Ws[16][64];

    const int tid = threadIdx.x;
    const int m0 = blockIdx.y * 64, n0 = blockIdx.x * 64;
    const int ty = tid >> 4, tx = tid & 15;
    const int am = tid >> 2, ak = (tid & 3) * 4;
    const int wk = tid >> 4, wn = (tid & 15) * 4;

    float acc[4][4] = {};
    const bool aval = (m0 + am) < M;

    for (int k0 = 0; k0 < K; k0 += 16) {
        float4 av = make_float4(0.f, 0.f, 0.f, 0.f);
        if (aval) av = *(const float4*)&A[(size_t)(m0 + am) * K + k0 + ak];
        As[ak + 0][am] = av.x; As[ak + 1][am] = av.y;
        As[ak + 2][am] = av.z; As[ak + 3][am] = av.w;

        float4 wv;
        if (n0 + wn + 3 < N) {
            wv = *(const float4*)&W[(size_t)(k0 + wk) * N + n0 + wn];
        } else {
            const float* wr = &W[(size_t)(k0 + wk) * N];
            wv.x = (n0 + wn + 0 < N) ? wr[n0 + wn + 0] : 0.f;
            wv.y = (n0 + wn + 1 < N) ? wr[n0 + wn + 1] : 0.f;
            wv.z = (n0 + wn + 2 < N) ? wr[n0 + wn + 2] : 0.f;
            wv.w = 0.f;
        }
        Ws[wk][wn + 0] = wv.x; Ws[wk][wn + 1] = wv.y;
        Ws[wk][wn + 2] = wv.z; Ws[wk][wn + 3] = wv.w;

        __syncthreads();
        #pragma unroll
        for (int kk = 0; kk < 16; kk++) {
            float4 a = *(const float4*)&As[kk][ty * 4];
            float4 b = *(const float4*)&Ws[kk][tx * 4];
            acc[0][0] += a.x * b.x; acc[0][1] += a.x * b.y; acc[0][2] += a.x * b.z; acc[0][3] += a.x * b.w;
            acc[1][0] += a.y * b.x; acc[1][1] += a.y * b.y; acc[1][2] += a.y * b.z; acc[1][3] += a.y * b.w;
            acc[2][0] += a.z * b.x; acc[2][1] += a.z * b.y; acc[2][2] += a.z * b.z; acc[2][3] += a.z * b.w;
            acc[3][0] += a.w * b.x; acc[3][1] += a.w * b.y; acc[3][2] += a.w * b.z; acc[3][3] += a.w * b.w;
        }
        __syncthreads();
    }

    #pragma unroll
    for (int i = 0; i < 4; i++) {
        int m = m0 + ty * 4 + i;
        if (m >= M) continue;
        #pragma unroll
        for (int j = 0; j < 4; j++) {
            int n = n0 + tx * 4 + j;
            if (n < N) {
                float v = acc[i][j] + bias[n];
                if (ACT) v = fmaxf(v, 0.f);
                C[(size_t)m * N + n] = v;
            }
        }
    }
}

// ---------------------------------------------------------------------------
// Tensor-core flash attention with relative-position bias.
// grid: (S/64, H, B), 256 threads = 8 warps.
// S phase: warp grid 4m x 2n over 64x32 score tile (Q frags persistent in regs).
// PV phase: warp grid 4m x 2n over 64x64 output tile (32-wide n per warp).
// ---------------------------------------------------------------------------
__global__ __launch_bounds__(256, 2) void attn_k(const float* __restrict__ Q,
                                                 const float* __restrict__ Km,
                                                 const float* __restrict__ V,
                                                 const float* __restrict__ rb,
                                                 float* __restrict__ O)
{
    // QSs holds Q tile (64x68) initially; reused as score tile Ss[64][36] afterwards
    __shared__ __align__(16) float QSs[64 * 68];
    __shared__ __align__(16) float Ks[32][68];
    __shared__ __align__(16) float Vs[32][72];
    __shared__ float m_s[64], l_s[64], al_s[64];
    __shared__ float rbias[96];

    float (*Ss)[36] = (float(*)[36])QSs;

    const int q0 = blockIdx.x * 64;
    const int h  = blockIdx.y;
    const int b  = blockIdx.z;

    const int tid  = threadIdx.x;
    const int warp = tid >> 5, lane = tid & 31;
    const int g    = lane >> 2, tg = lane & 3;
    const int wmS  = (warp >> 1) * 16, wnS = (warp & 1) * 16;
    const int wmP  = (warp >> 1) * 16, wnP = (warp & 1) * 32;

    // load Q tile (64 rows x 64 d)
    #pragma unroll
    for (int r = 0; r < 4; r++) {
        int lin = tid + r * 256;
        int qr = lin >> 4, dc = (lin & 15) * 4;
        float4 v = *(const float4*)&Q[((size_t)(b * S_) + q0 + qr) * D_ + h * DK_ + dc];
        QSs[qr * 68 + dc + 0] = v.x; QSs[qr * 68 + dc + 1] = v.y;
        QSs[qr * 68 + dc + 2] = v.z; QSs[qr * 68 + dc + 3] = v.w;
    }
    if (tid < 64) { m_s[tid] = -1e30f; l_s[tid] = 0.f; }
    __syncthreads();

    // persistent Q fragments (tf32): 8 k-steps x 4 regs
    unsigned qa[8][4];
    #pragma unroll
    for (int ks = 0; ks < 8; ks++) {
        int r = wmS + g;
        qa[ks][0] = tf32u(QSs[(r    ) * 68 + ks * 8 + tg    ]);
        qa[ks][1] = tf32u(QSs[(r + 8) * 68 + ks * 8 + tg    ]);
        qa[ks][2] = tf32u(QSs[(r    ) * 68 + ks * 8 + tg + 4]);
        qa[ks][3] = tf32u(QSs[(r + 8) * 68 + ks * 8 + tg + 4]);
    }

    float oacc[4][4];
    #pragma unroll
    for (int i = 0; i < 4; i++)
        #pragma unroll
        for (int j = 0; j < 4; j++) oacc[i][j] = 0.f;

    for (int j0 = 0; j0 < S_; j0 += 32) {
        __syncthreads();   // previous chunk's Ss/Vs consumers done (and Q frag loads, iter 0)

        // fill K, V chunk (32 rows x 64 d each) — coalesced, no transpose
        #pragma unroll
        for (int r = 0; r < 2; r++) {
            int lin = tid + r * 256;
            int kr = lin >> 4, dc = (lin & 15) * 4;
            size_t gi = ((size_t)(b * S_) + j0 + kr) * D_ + h * DK_ + dc;
            *(float4*)&Ks[kr][dc] = *(const float4*)&Km[gi];
            *(float4*)&Vs[kr][dc] = *(const float4*)&V[gi];
        }
        if (tid < 95) rbias[tid] = rb[(j0 - q0 + 448 + tid) * H_ + h];
        __syncthreads();

        // S = Q @ K^T : per-warp 16x16, acc 2 n-tiles
        float sc[2][4];
        #pragma unroll
        for (int nt = 0; nt < 2; nt++)
            #pragma unroll
            for (int r = 0; r < 4; r++) sc[nt][r] = 0.f;

        #pragma unroll
        for (int ks = 0; ks < 8; ks++) {
            unsigned kb[2][2];
            #pragma unroll
            for (int nt = 0; nt < 2; nt++) {
                int c = wnS + nt * 8 + g;
                kb[nt][0] = tf32u(Ks[c][ks * 8 + tg    ]);
                kb[nt][1] = tf32u(Ks[c][ks * 8 + tg + 4]);
            }
            #pragma unroll
            for (int nt = 0; nt < 2; nt++)
                MMA_TF32(sc[nt], qa[ks][0], qa[ks][1], qa[ks][2], qa[ks][3],
                         kb[nt][0], kb[nt][1]);
        }
        // write scores with scale + rel bias  (bias idx = 63 + col - row)
        #pragma unroll
        for (int nt = 0; nt < 2; nt++) {
            int col = wnS + nt * 8 + tg * 2;
            int r0  = wmS + g;
            Ss[r0    ][col    ] = sc[nt][0] * 0.125f + rbias[63 + col - r0];
            Ss[r0    ][col + 1] = sc[nt][1] * 0.125f + rbias[64 + col - r0];
            Ss[r0 + 8][col    ] = sc[nt][2] * 0.125f + rbias[55 + col - r0];
            Ss[r0 + 8][col + 1] = sc[nt][3] * 0.125f + rbias[56 + col - r0];
        }
        __syncthreads();

        // online softmax per row
        if (tid < 64) {
            float mo = m_s[tid], cm = mo;
            #pragma unroll
            for (int c = 0; c < 32; c++) cm = fmaxf(cm, Ss[tid][c]);
            float al = expf(mo - cm);
            float rs = 0.f;
            #pragma unroll
            for (int c = 0; c < 32; c++) {
                float p = expf(Ss[tid][c] - cm);
                Ss[tid][c] = p;
                rs += p;
            }
            l_s[tid] = l_s[tid] * al + rs;
            m_s[tid] = cm;
            al_s[tid] = al;
        }
        __syncthreads();

        // PV: rescale + accumulate, per-warp 16x32
        float al0 = al_s[wmP + g], al1 = al_s[wmP + g + 8];
        #pragma unroll
        for (int nt = 0; nt < 4; nt++) {
            oacc[nt][0] *= al0; oacc[nt][1] *= al0;
            oacc[nt][2] *= al1; oacc[nt][3] *= al1;
        }
        #pragma unroll
        for (int ks = 0; ks < 4; ks++) {
            unsigned pa[4];
            int r = wmP + g;
            pa[0] = tf32u(Ss[r    ][ks * 8 + tg    ]);
            pa[1] = tf32u(Ss[r + 8][ks * 8 + tg    ]);
            pa[2] = tf32u(Ss[r    ][ks * 8 + tg + 4]);
            pa[3] = tf32u(Ss[r + 8][ks * 8 + tg + 4]);
            #pragma unroll
            for (int nt = 0; nt < 4; nt++) {
                unsigned vb0 = tf32u(Vs[ks * 8 + tg    ][wnP + nt * 8 + g]);
                unsigned vb1 = tf32u(Vs[ks * 8 + tg + 4][wnP + nt * 8 + g]);
                MMA_TF32(oacc[nt], pa[0], pa[1], pa[2], pa[3], vb0, vb1);
            }
        }
    }

    // epilogue
    float inv0 = 1.f / l_s[wmP + g];
    float inv1 = 1.f / l_s[wmP + g + 8];
    #pragma unroll
    for (int nt = 0; nt < 4; nt++) {
        int col = wnP + nt * 8 + tg * 2;
        size_t o0 = ((size_t)(b * S_) + q0 + wmP + g    ) * D_ + h * DK_ + col;
        size_t o1 = ((size_t)(b * S_) + q0 + wmP + g + 8) * D_ + h * DK_ + col;
        *(float2*)&O[o0] = make_float2(oacc[nt][0] * inv0, oacc[nt][1] * inv0);
        *(float2*)&O[o1] = make_float2(oacc[nt][2] * inv1, oacc[nt][3] * inv1);
    }
}

// ---------------------------------------------------------------------------
// Fused residual-add + LayerNorm
// ---------------------------------------------------------------------------
__global__ __launch_bounds__(256) void ln_k(const float* __restrict__ X,
                                            const float* __restrict__ R,
                                            const float* __restrict__ g,
                                            const float* __restrict__ be,
                                            float* __restrict__ Y)
{
    __shared__ float red[256];
    const int row = blockIdx.x, tid = threadIdx.x;
    const size_t off = (size_t)row * D_;

    float v0 = X[off + tid      ] + R[off + tid      ];
    float v1 = X[off + tid + 256] + R[off + tid + 256];
    float v2 = X[off + tid + 512] + R[off + tid + 512];

    red[tid] = v0 + v1 + v2;
    __syncthreads();
    #pragma unroll
    for (int s = 128; s > 0; s >>= 1) {
        if (tid < s) red[tid] += red[tid + s];
        __syncthreads();
    }
    float mean = red[0] * (1.f / (float)D_);
    __syncthreads();

    float d0 = v0 - mean, d1 = v1 - mean, d2 = v2 - mean;
    red[tid] = d0 * d0 + d1 * d1 + d2 * d2;
    __syncthreads();
    #pragma unroll
    for (int s = 128; s > 0; s >>= 1) {
        if (tid < s) red[tid] += red[tid + s];
        __syncthreads();
    }
    float inv = rsqrtf(red[0] * (1.f / (float)D_) + 1e-5f);

    Y[off + tid      ] = d0 * inv * g[tid      ] + be[tid      ];
    Y[off + tid + 256] = d1 * inv * g[tid + 256] + be[tid + 256];
    Y[off + tid + 512] = d2 * inv * g[tid + 512] + be[tid + 512];
}

// ---------------------------------------------------------------------------
// Mean pooling over sequence
// ---------------------------------------------------------------------------
__global__ __launch_bounds__(256) void pool_k(const float* __restrict__ X,
                                              float* __restrict__ P)
{
    int b = blockIdx.y;
    int d = blockIdx.x * 256 + threadIdx.x;
    float s = 0.f;
    for (int sq = 0; sq < S_; sq++)
        s += X[(((size_t)b * S_) + sq) * D_ + d];
    P[(size_t)b * D_ + d] = s * (1.f / (float)S_);
}

// ---------------------------------------------------------------------------
extern "C" void kernel_launch(void* const* d_in, const int* in_sizes, int n_in,
                              void* d_out, int out_size)
{
    (void)in_sizes; (void)n_in; (void)out_size;

    const int*   ids = (const int*)  d_in[0];
    const float* emb = (const float*)d_in[1];
    const float* wq  = (const float*)d_in[2];
    const float* bq  = (const float*)d_in[3];
    const float* wk  = (const float*)d_in[4];
    const float* bk  = (const float*)d_in[5];
    const float* wv  = (const float*)d_in[6];
    const float* bv  = (const float*)d_in[7];
    const float* wo  = (const float*)d_in[8];
    const float* bo  = (const float*)d_in[9];
    const float* rb  = (const float*)d_in[10];
    const float* w1  = (const float*)d_in[11];
    const float* b1  = (const float*)d_in[12];
    const float* w2  = (const float*)d_in[13];
    const float* b2  = (const float*)d_in[14];
    const float* g1  = (const float*)d_in[15];
    const float* be1 = (const float*)d_in[16];
    const float* g2  = (const float*)d_in[17];
    const float* be2 = (const float*)d_in[18];
    const float* cw1 = (const float*)d_in[19];
    const float* cb1 = (const float*)d_in[20];
    const float* cw2 = (const float*)d_in[21];
    const float* cb2 = (const float*)d_in[22];
    float* out = (float*)d_out;

    float* base = nullptr;
    cudaGetSymbolAddress((void**)&base, g_scratch);

    float* X  = base;
    float* Y  = base + 1 * (size_t)BSD;
    float* Qb = base + 2 * (size_t)BSD;
    float* Kb = base + 3 * (size_t)BSD;
    float* Vb = base + 4 * (size_t)BSD;
    float* Cb = base + 5 * (size_t)BSD;
    float* Ab = base + 6 * (size_t)BSD;
    float* Hb = base + 7 * (size_t)BSD;
    float* Pp = Hb + (size_t)BSF;
    float* Ch = Pp + B_ * D_;

    embed_k<<<dim3(B_ * S_, 3), 256>>>(ids, emb, X);

    const int M = B_ * S_;                   // 8192
    dim3 gProj(D_ / 128,  M / 128);          // (6, 64)
    dim3 gQKV (3 * D_ / 128, M / 128);       // (18, 64)
    dim3 gF1  (DFF_ / 128, M / 128);         // (24, 64)

    for (int l = 0; l < L_; l++) {
        size_t oDD = (size_t)l * D_ * D_;
        gemm_qkv<<<gQKV, 256>>>(X, wq + oDD, wk + oDD, wv + oDD,
                                bq + l * D_, bk + l * D_, bv + l * D_,
                                Qb, Kb, Vb);
        attn_k<<<dim3(S_ / 64, H_, B_), 256>>>(Qb, Kb, Vb,
                                               rb + (size_t)l * (2 * S_ - 1) * H_, Cb);
        gemm_tc<0><<<gProj, 256>>>(Cb, wo + oDD, bo + l * D_, Ab, D_, D_);
        ln_k<<<M, 256>>>(X, Ab, g1 + l * D_, be1 + l * D_, Y);
        gemm_tc<1><<<gF1, 256>>>(Y, w1 + (size_t)l * D_ * DFF_, b1 + l * DFF_, Hb, DFF_, D_);
        gemm_tc<0><<<gProj, 256>>>(Hb, w2 + (size_t)l * DFF_ * D_, b2 + l * D_, Ab, D_, DFF_);
        ln_k<<<M, 256>>>(Y, Ab, g2 + l * D_, be2 + l * D_, X);
    }

    pool_k<<<dim3(3, B_), 256>>>(X, Pp);
    gemm_k<1><<<dim3(6, 1), 256>>>(Pp, cw1, cb1, Ch, B_, D_ / 2, D_);
    gemm_k<0><<<dim3(2, 1), 256>>>(Ch, cw2, cb2, out, B_, NC_, D_ / 2);
}

// round 12
// speedup vs baseline: 3.4742x; 1.0886x over previous
#include <cuda_runtime.h>

// ---- problem constants ----
#define B_   16
#define S_   512
#define D_   768
#define H_   12
#define DK_  64
#define DFF_ 3072
#define L_   12
#define NC_  100

#define BSD  (B_*S_*D_)
#define BSF  (B_*S_*DFF_)

__device__ __align__(16) float g_scratch[7*(size_t)BSD + (size_t)BSF + B_*D_ + B_*(D_/2)];

__device__ __forceinline__ unsigned tf32u(float x) {
    unsigned u;
    asm("cvt.rna.tf32.f32 %0, %1;" : "=r"(u) : "f"(x));
    return u;
}

__device__ __forceinline__ void cpa16(void* dst, const void* src) {
    unsigned d = (unsigned)__cvta_generic_to_shared(dst);
    asm volatile("cp.async.cg.shared.global [%0], [%1], 16;\n" :: "r"(d), "l"(src));
}

#define CP_COMMIT() asm volatile("cp.async.commit_group;\n" ::: "memory")
#define CP_WAIT(n)  asm volatile("cp.async.wait_group %0;\n" :: "n"(n) : "memory")

#define MMA_TF32(d, a0,a1,a2,a3, b0,b1) \
    asm volatile("mma.sync.aligned.m16n8k8.row.col.f32.tf32.tf32.f32 " \
                 "{%0,%1,%2,%3}, {%4,%5,%6,%7}, {%8,%9}, {%0,%1,%2,%3};\n" \
      : "+f"((d)[0]), "+f"((d)[1]), "+f"((d)[2]), "+f"((d)[3]) \
      : "r"(a0), "r"(a1), "r"(a2), "r"(a3), "r"(b0), "r"(b1))

// dynamic smem layout for the 3-stage BK=32 GEMM
#define GS_STAGES 3
#define AS_STRIDE 36    // 32 + 4 pad  (144 B, 16B-aligned rows; frag banks 4g+tg)
#define BS_STRIDE 136   // 128 + 8 pad (544 B, 16B-aligned rows; frag banks 8tg+g)
#define AS_ELEMS  (128 * AS_STRIDE)
#define BS_ELEMS  (32 * BS_STRIDE)
#define GS_SMEM_BYTES ((GS_STAGES * (AS_ELEMS + BS_ELEMS)) * sizeof(float))

// ---------------------------------------------------------------------------
// Embedding + sinusoidal positional encoding
// ---------------------------------------------------------------------------
__global__ __launch_bounds__(256) void embed_k(const int* __restrict__ ids,
                                               const float* __restrict__ emb,
                                               float* __restrict__ X)
{
    int bs = blockIdx.x;
    int d  = blockIdx.y * 256 + threadIdx.x;
    int s  = bs & (S_ - 1);
    int tok = ids[bs];
    int i2 = (d >> 1) * 2;
    float freq = expf((float)i2 * (-9.210340371976184f / (float)D_));
    float ang  = (float)s * freq;
    float pe   = (d & 1) ? cosf(ang) : sinf(ang);
    X[(size_t)bs * D_ + d] = emb[(size_t)tok * D_ + d] + pe;
}

// ---------------------------------------------------------------------------
// TF32 tensor-core GEMM core: C[m0:+128, n0:+128] = act(A @ W + bias)
// 128x128 block tile, BK=32, 3-stage cp.async pipeline, wait_group 1.
// 256 threads = 8 warps (2m x 4n), warp tile 64x32, mma.m16n8k8.
// Requires M%128==0 (call site), N%128==0, K%32==0.
// ---------------------------------------------------------------------------
template<int ACT>
__device__ __forceinline__ void gemm_core(const float* __restrict__ A,
                                          const float* __restrict__ W,
                                          const float* __restrict__ bias,
                                          float* __restrict__ C,
                                          int N, int K, int m0, int n0)
{
    extern __shared__ __align__(16) float smem[];
    float* As = smem;                              // [st][128][AS_STRIDE]
    float* Bs = smem + GS_STAGES * AS_ELEMS;       // [st][32][BS_STRIDE]

    const int tid  = threadIdx.x;
    const int warp = tid >> 5, lane = tid & 31;
    const int wm   = (warp >> 2) * 64;
    const int wn   = (warp & 3) * 32;
    const int g    = lane >> 2;
    const int tg   = lane & 3;

    float acc[4][4][4];
    #pragma unroll
    for (int i = 0; i < 4; i++)
        #pragma unroll
        for (int j = 0; j < 4; j++)
            #pragma unroll
            for (int r = 0; r < 4; r++) acc[i][j][r] = 0.f;

    // loader maps: 4 x 16B chunks per thread for each of A, B
    // A: chunk c = tid + i*256 -> row c>>3 (0..127), kcol (c&7)*4
    // B: chunk c = tid + i*256 -> krow c>>5 (0..31), ncol (c&31)*4
    const int nk = K >> 5;

    auto load_stage = [&](int stage, int k0) {
        float* as = As + stage * AS_ELEMS;
        float* bs = Bs + stage * BS_ELEMS;
        #pragma unroll
        for (int i = 0; i < 4; i++) {
            int c = tid + i * 256;
            int ar = c >> 3, akc = (c & 7) * 4;
            cpa16(&as[ar * AS_STRIDE + akc], &A[(size_t)(m0 + ar) * K + k0 + akc]);
        }
        #pragma unroll
        for (int i = 0; i < 4; i++) {
            int c = tid + i * 256;
            int br = c >> 5, bnc = (c & 31) * 4;
            cpa16(&bs[br * BS_STRIDE + bnc], &W[(size_t)(k0 + br) * N + n0 + bnc]);
        }
        CP_COMMIT();
    };

    load_stage(0, 0);
    if (nk > 1) load_stage(1, 32);

    int st = 0;
    for (int it = 0; it < nk; it++) {
        CP_WAIT(1);           // stage `it` complete; stage `it+1` may still fly
        __syncthreads();      // visibility across threads + buffer reuse safety
        if (it + 2 < nk) load_stage((it + 2) % GS_STAGES, (it + 2) << 5);

        const float* as = As + st * AS_ELEMS;
        const float* bs = Bs + st * BS_ELEMS;
        #pragma unroll
        for (int kk = 0; kk < 32; kk += 8) {
            unsigned a[4][4], b[4][2];
            #pragma unroll
            for (int mt = 0; mt < 4; mt++) {
                int r = wm + mt * 16 + g;
                a[mt][0] = tf32u(as[(r    ) * AS_STRIDE + kk + tg    ]);
                a[mt][1] = tf32u(as[(r + 8) * AS_STRIDE + kk + tg    ]);
                a[mt][2] = tf32u(as[(r    ) * AS_STRIDE + kk + tg + 4]);
                a[mt][3] = tf32u(as[(r + 8) * AS_STRIDE + kk + tg + 4]);
            }
            #pragma unroll
            for (int nt = 0; nt < 4; nt++) {
                int c = wn + nt * 8 + g;
                b[nt][0] = tf32u(bs[(kk + tg    ) * BS_STRIDE + c]);
                b[nt][1] = tf32u(bs[(kk + tg + 4) * BS_STRIDE + c]);
            }
            #pragma unroll
            for (int mt = 0; mt < 4; mt++)
                #pragma unroll
                for (int nt = 0; nt < 4; nt++)
                    MMA_TF32(acc[mt][nt], a[mt][0], a[mt][1], a[mt][2], a[mt][3],
                             b[nt][0], b[nt][1]);
        }
        st = (st + 1) % GS_STAGES;
    }

    #pragma unroll
    for (int mt = 0; mt < 4; mt++) {
        int r0 = m0 + wm + mt * 16 + g;
        #pragma unroll
        for (int nt = 0; nt < 4; nt++) {
            int cb = n0 + wn + nt * 8 + tg * 2;
            float b0 = bias[cb], b1 = bias[cb + 1];
            float v0 = acc[mt][nt][0] + b0;
            float v1 = acc[mt][nt][1] + b1;
            float v2 = acc[mt][nt][2] + b0;
            float v3 = acc[mt][nt][3] + b1;
            if (ACT) {
                v0 = fmaxf(v0, 0.f); v1 = fmaxf(v1, 0.f);
                v2 = fmaxf(v2, 0.f); v3 = fmaxf(v3, 0.f);
            }
            *(float2*)&C[(size_t)r0 * N + cb]       = make_float2(v0, v1);
            *(float2*)&C[(size_t)(r0 + 8) * N + cb] = make_float2(v2, v3);
        }
    }
}

template<int ACT>
__global__ __launch_bounds__(256, 2) void gemm_tc(const float* __restrict__ A,
                                                  const float* __restrict__ W,
                                                  const float* __restrict__ bias,
                                                  float* __restrict__ C,
                                                  int N, int K)
{
    gemm_core<ACT>(A, W, bias, C, N, K, blockIdx.y * 128, blockIdx.x * 128);
}

// Fused QKV: grid.x = 18 (which = bx/6, n0 = (bx%6)*128)
__global__ __launch_bounds__(256, 2) void gemm_qkv(const float* __restrict__ X,
                                                   const float* __restrict__ wq,
                                                   const float* __restrict__ wk,
                                                   const float* __restrict__ wv,
                                                   const float* __restrict__ bq,
                                                   const float* __restrict__ bk,
                                                   const float* __restrict__ bv,
                                                   float* __restrict__ Qb,
                                                   float* __restrict__ Kb,
                                                   float* __restrict__ Vb)
{
    const int which = blockIdx.x / 6;
    const int n0 = (blockIdx.x % 6) * 128;
    const float* W  = (which == 0) ? wq : (which == 1) ? wk : wv;
    const float* bi = (which == 0) ? bq : (which == 1) ? bk : bv;
    float*       C  = (which == 0) ? Qb : (which == 1) ? Kb : Vb;
    gemm_core<0>(X, W, bi, C, D_, D_, blockIdx.y * 128, n0);
}

// ---------------------------------------------------------------------------
// Small fp32 GEMM (classifier only)
// ---------------------------------------------------------------------------
template<int ACT>
__global__ __launch_bounds__(256) void gemm_k(const float* __restrict__ A,
                                              const float* __restrict__ W,
                                              const float* __restrict__ bias,
                                              float* __restrict__ C,
                                              int M, int N, int K)
{
    __shared__ float As[16][64];
    __shared__ float Ws[16][64];

    const int tid = threadIdx.x;
    const int m0 = blockIdx.y * 64, n0 = blockIdx.x * 64;
    const int ty = tid >> 4, tx = tid & 15;
    const int am = tid >> 2, ak = (tid & 3) * 4;
    const int wk = tid >> 4, wn = (tid & 15) * 4;

    float acc[4][4] = {};
    const bool aval = (m0 + am) < M;

    for (int k0 = 0; k0 < K; k0 += 16) {
        float4 av = make_float4(0.f, 0.f, 0.f, 0.f);
        if (aval) av = *(const float4*)&A[(size_t)(m0 + am) * K + k0 + ak];
        As[ak + 0][am] = av.x; As[ak + 1][am] = av.y;
        As[ak + 2][am] = av.z; As[ak + 3][am] = av.w;

        float4 wv;
        if (n0 + wn + 3 < N) {
            wv = *(const float4*)&W[(size_t)(k0 + wk) * N + n0 + wn];
        } else {
            const float* wr = &W[(size_t)(k0 + wk) * N];
            wv.x = (n0 + wn + 0 < N) ? wr[n0 + wn + 0] : 0.f;
            wv.y = (n0 + wn + 1 < N) ? wr[n0 + wn + 1] : 0.f;
            wv.z = (n0 + wn + 2 < N) ? wr[n0 + wn + 2] : 0.f;
            wv.w = 0.f;
        }
        Ws[wk][wn + 0] = wv.x; Ws[wk][wn + 1] = wv.y;
        Ws[wk][wn + 2] = wv.z; Ws[wk][wn + 3] = wv.w;

        __syncthreads();
        #pragma unroll
        for (int kk = 0; kk < 16; kk++) {
            float4 a = *(const float4*)&As[kk][ty * 4];
            float4 b = *(const float4*)&Ws[kk][tx * 4];
            acc[0][0] += a.x * b.x; acc[0][1] += a.x * b.y; acc[0][2] += a.x * b.z; acc[0][3] += a.x * b.w;
            acc[1][0] += a.y * b.x; acc[1][1] += a.y * b.y; acc[1][2] += a.y * b.z; acc[1][3] += a.y * b.w;
            acc[2][0] += a.z * b.x; acc[2][1] += a.z * b.y; acc[2][2] += a.z * b.z; acc[2][3] += a.z * b.w;
            acc[3][0] += a.w * b.x; acc[3][1] += a.w * b.y; acc[3][2] += a.w * b.z; acc[3][3] += a.w * b.w;
        }
        __syncthreads();
    }

    #pragma unroll
    for (int i = 0; i < 4; i++) {
        int m = m0 + ty * 4 + i;
        if (m >= M) continue;
        #pragma unroll
        for (int j = 0; j < 4; j++) {
            int n = n0 + tx * 4 + j;
            if (n < N) {
                float v = acc[i][j] + bias[n];
                if (ACT) v = fmaxf(v, 0.f);
                C[(size_t)m * N + n] = v;
            }
        }
    }
}

// ---------------------------------------------------------------------------
// Tensor-core flash attention with relative-position bias (unchanged from R8).
// ---------------------------------------------------------------------------
__global__ __launch_bounds__(256, 2) void attn_k(const float* __restrict__ Q,
                                                 const float* __restrict__ Km,
                                                 const float* __restrict__ V,
                                                 const float* __restrict__ rb,
                                                 float* __restrict__ O)
{
    __shared__ __align__(16) float QSs[64 * 68];
    __shared__ __align__(16) float Ks[32][68];
    __shared__ __align__(16) float Vs[32][72];
    __shared__ float m_s[64], l_s[64], al_s[64];
    __shared__ float rbias[96];

    float (*Ss)[36] = (float(*)[36])QSs;

    const int q0 = blockIdx.x * 64;
    const int h  = blockIdx.y;
    const int b  = blockIdx.z;

    const int tid  = threadIdx.x;
    const int warp = tid >> 5, lane = tid & 31;
    const int g    = lane >> 2, tg = lane & 3;
    const int wmS  = (warp >> 1) * 16, wnS = (warp & 1) * 16;
    const int wmP  = (warp >> 1) * 16, wnP = (warp & 1) * 32;

    #pragma unroll
    for (int r = 0; r < 4; r++) {
        int lin = tid + r * 256;
        int qr = lin >> 4, dc = (lin & 15) * 4;
        float4 v = *(const float4*)&Q[((size_t)(b * S_) + q0 + qr) * D_ + h * DK_ + dc];
        QSs[qr * 68 + dc + 0] = v.x; QSs[qr * 68 + dc + 1] = v.y;
        QSs[qr * 68 + dc + 2] = v.z; QSs[qr * 68 + dc + 3] = v.w;
    }
    if (tid < 64) { m_s[tid] = -1e30f; l_s[tid] = 0.f; }
    __syncthreads();

    unsigned qa[8][4];
    #pragma unroll
    for (int ks = 0; ks < 8; ks++) {
        int r = wmS + g;
        qa[ks][0] = tf32u(QSs[(r    ) * 68 + ks * 8 + tg    ]);
        qa[ks][1] = tf32u(QSs[(r + 8) * 68 + ks * 8 + tg    ]);
        qa[ks][2] = tf32u(QSs[(r    ) * 68 + ks * 8 + tg + 4]);
        qa[ks][3] = tf32u(QSs[(r + 8) * 68 + ks * 8 + tg + 4]);
    }

    float oacc[4][4];
    #pragma unroll
    for (int i = 0; i < 4; i++)
        #pragma unroll
        for (int j = 0; j < 4; j++) oacc[i][j] = 0.f;

    for (int j0 = 0; j0 < S_; j0 += 32) {
        __syncthreads();

        #pragma unroll
        for (int r = 0; r < 2; r++) {
            int lin = tid + r * 256;
            int kr = lin >> 4, dc = (lin & 15) * 4;
            size_t gi = ((size_t)(b * S_) + j0 + kr) * D_ + h * DK_ + dc;
            *(float4*)&Ks[kr][dc] = *(const float4*)&Km[gi];
            *(float4*)&Vs[kr][dc] = *(const float4*)&V[gi];
        }
        if (tid < 95) rbias[tid] = rb[(j0 - q0 + 448 + tid) * H_ + h];
        __syncthreads();

        float sc[2][4];
        #pragma unroll
        for (int nt = 0; nt < 2; nt++)
            #pragma unroll
            for (int r = 0; r < 4; r++) sc[nt][r] = 0.f;

        #pragma unroll
        for (int ks = 0; ks < 8; ks++) {
            unsigned kb[2][2];
            #pragma unroll
            for (int nt = 0; nt < 2; nt++) {
                int c = wnS + nt * 8 + g;
                kb[nt][0] = tf32u(Ks[c][ks * 8 + tg    ]);
                kb[nt][1] = tf32u(Ks[c][ks * 8 + tg + 4]);
            }
            #pragma unroll
            for (int nt = 0; nt < 2; nt++)
                MMA_TF32(sc[nt], qa[ks][0], qa[ks][1], qa[ks][2], qa[ks][3],
                         kb[nt][0], kb[nt][1]);
        }
        #pragma unroll
        for (int nt = 0; nt < 2; nt++) {
            int col = wnS + nt * 8 + tg * 2;
            int r0  = wmS + g;
            Ss[r0    ][col    ] = sc[nt][0] * 0.125f + rbias[63 + col - r0];
            Ss[r0    ][col + 1] = sc[nt][1] * 0.125f + rbias[64 + col - r0];
            Ss[r0 + 8][col    ] = sc[nt][2] * 0.125f + rbias[55 + col - r0];
            Ss[r0 + 8][col + 1] = sc[nt][3] * 0.125f + rbias[56 + col - r0];
        }
        __syncthreads();

        if (tid < 64) {
            float mo = m_s[tid], cm = mo;
            #pragma unroll
            for (int c = 0; c < 32; c++) cm = fmaxf(cm, Ss[tid][c]);
            float al = expf(mo - cm);
            float rs = 0.f;
            #pragma unroll
            for (int c = 0; c < 32; c++) {
                float p = expf(Ss[tid][c] - cm);
                Ss[tid][c] = p;
                rs += p;
            }
            l_s[tid] = l_s[tid] * al + rs;
            m_s[tid] = cm;
            al_s[tid] = al;
        }
        __syncthreads();

        float al0 = al_s[wmP + g], al1 = al_s[wmP + g + 8];
        #pragma unroll
        for (int nt = 0; nt < 4; nt++) {
            oacc[nt][0] *= al0; oacc[nt][1] *= al0;
            oacc[nt][2] *= al1; oacc[nt][3] *= al1;
        }
        #pragma unroll
        for (int ks = 0; ks < 4; ks++) {
            unsigned pa[4];
            int r = wmP + g;
            pa[0] = tf32u(Ss[r    ][ks * 8 + tg    ]);
            pa[1] = tf32u(Ss[r + 8][ks * 8 + tg    ]);
            pa[2] = tf32u(Ss[r    ][ks * 8 + tg + 4]);
            pa[3] = tf32u(Ss[r + 8][ks * 8 + tg + 4]);
            #pragma unroll
            for (int nt = 0; nt < 4; nt++) {
                unsigned vb0 = tf32u(Vs[ks * 8 + tg    ][wnP + nt * 8 + g]);
                unsigned vb1 = tf32u(Vs[ks * 8 + tg + 4][wnP + nt * 8 + g]);
                MMA_TF32(oacc[nt], pa[0], pa[1], pa[2], pa[3], vb0, vb1);
            }
        }
    }

    float inv0 = 1.f / l_s[wmP + g];
    float inv1 = 1.f / l_s[wmP + g + 8];
    #pragma unroll
    for (int nt = 0; nt < 4; nt++) {
        int col = wnP + nt * 8 + tg * 2;
        size_t o0 = ((size_t)(b * S_) + q0 + wmP + g    ) * D_ + h * DK_ + col;
        size_t o1 = ((size_t)(b * S_) + q0 + wmP + g + 8) * D_ + h * DK_ + col;
        *(float2*)&O[o0] = make_float2(oacc[nt][0] * inv0, oacc[nt][1] * inv0);
        *(float2*)&O[o1] = make_float2(oacc[nt][2] * inv1, oacc[nt][3] * inv1);
    }
}

// ---------------------------------------------------------------------------
// Fused residual-add + LayerNorm (warp-shuffle reduction, 2 barriers)
// ---------------------------------------------------------------------------
__global__ __launch_bounds__(256) void ln_k(const float* __restrict__ X,
                                            const float* __restrict__ R,
                                            const float* __restrict__ g,
                                            const float* __restrict__ be,
                                            float* __restrict__ Y)
{
    __shared__ float ws1[8], ws2[8];
    const int row = blockIdx.x, tid = threadIdx.x;
    const int warp = tid >> 5, lane = tid & 31;
    const size_t off = (size_t)row * D_;

    float v0 = X[off + tid      ] + R[off + tid      ];
    float v1 = X[off + tid + 256] + R[off + tid + 256];
    float v2 = X[off + tid + 512] + R[off + tid + 512];

    float s = v0 + v1 + v2;
    #pragma unroll
    for (int o = 16; o > 0; o >>= 1) s += __shfl_xor_sync(0xffffffffu, s, o);
    if (lane == 0) ws1[warp] = s;
    __syncthreads();
    float mean = (ws1[0] + ws1[1] + ws1[2] + ws1[3] +
                  ws1[4] + ws1[5] + ws1[6] + ws1[7]) * (1.f / (float)D_);

    float d0 = v0 - mean, d1 = v1 - mean, d2 = v2 - mean;
    float q = d0 * d0 + d1 * d1 + d2 * d2;
    #pragma unroll
    for (int o = 16; o > 0; o >>= 1) q += __shfl_xor_sync(0xffffffffu, q, o);
    if (lane == 0) ws2[warp] = q;
    __syncthreads();
    float inv = rsqrtf((ws2[0] + ws2[1] + ws2[2] + ws2[3] +
                        ws2[4] + ws2[5] + ws2[6] + ws2[7]) * (1.f / (float)D_) + 1e-5f);

    Y[off + tid      ] = d0 * inv * g[tid      ] + be[tid      ];
    Y[off + tid + 256] = d1 * inv * g[tid + 256] + be[tid + 256];
    Y[off + tid + 512] = d2 * inv * g[tid + 512] + be[tid + 512];
}

// ---------------------------------------------------------------------------
// Mean pooling over sequence
// ---------------------------------------------------------------------------
__global__ __launch_bounds__(256) void pool_k(const float* __restrict__ X,
                                              float* __restrict__ P)
{
    int b = blockIdx.y;
    int d = blockIdx.x * 256 + threadIdx.x;
    float s = 0.f;
    for (int sq = 0; sq < S_; sq++)
        s += X[(((size_t)b * S_) + sq) * D_ + d];
    P[(size_t)b * D_ + d] = s * (1.f / (float)S_);
}

// ---------------------------------------------------------------------------
extern "C" void kernel_launch(void* const* d_in, const int* in_sizes, int n_in,
                              void* d_out, int out_size)
{
    (void)in_sizes; (void)n_in; (void)out_size;

    const int*   ids = (const int*)  d_in[0];
    const float* emb = (const float*)d_in[1];
    const float* wq  = (const float*)d_in[2];
    const float* bq  = (const float*)d_in[3];
    const float* wk  = (const float*)d_in[4];
    const float* bk  = (const float*)d_in[5];
    const float* wv  = (const float*)d_in[6];
    const float* bv  = (const float*)d_in[7];
    const float* wo  = (const float*)d_in[8];
    const float* bo  = (const float*)d_in[9];
    const float* rb  = (const float*)d_in[10];
    const float* w1  = (const float*)d_in[11];
    const float* b1  = (const float*)d_in[12];
    const float* w2  = (const float*)d_in[13];
    const float* b2  = (const float*)d_in[14];
    const float* g1  = (const float*)d_in[15];
    const float* be1 = (const float*)d_in[16];
    const float* g2  = (const float*)d_in[17];
    const float* be2 = (const float*)d_in[18];
    const float* cw1 = (const float*)d_in[19];
    const float* cb1 = (const float*)d_in[20];
    const float* cw2 = (const float*)d_in[21];
    const float* cb2 = (const float*)d_in[22];
    float* out = (float*)d_out;

    float* base = nullptr;
    cudaGetSymbolAddress((void**)&base, g_scratch);

    float* X  = base;
    float* Y  = base + 1 * (size_t)BSD;
    float* Qb = base + 2 * (size_t)BSD;
    float* Kb = base + 3 * (size_t)BSD;
    float* Vb = base + 4 * (size_t)BSD;
    float* Cb = base + 5 * (size_t)BSD;
    float* Ab = base + 6 * (size_t)BSD;
    float* Hb = base + 7 * (size_t)BSD;
    float* Pp = Hb + (size_t)BSF;
    float* Ch = Pp + B_ * D_;

    // opt-in >48KB dynamic smem (host-side attribute; legal during capture)
    cudaFuncSetAttribute(gemm_tc<0>, cudaFuncAttributeMaxDynamicSharedMemorySize, (int)GS_SMEM_BYTES);
    cudaFuncSetAttribute(gemm_tc<1>, cudaFuncAttributeMaxDynamicSharedMemorySize, (int)GS_SMEM_BYTES);
    cudaFuncSetAttribute(gemm_qkv,   cudaFuncAttributeMaxDynamicSharedMemorySize, (int)GS_SMEM_BYTES);

    embed_k<<<dim3(B_ * S_, 3), 256>>>(ids, emb, X);

    const int M = B_ * S_;                   // 8192
    dim3 gProj(D_ / 128,  M / 128);          // (6, 64)
    dim3 gQKV (3 * D_ / 128, M / 128);       // (18, 64)
    dim3 gF1  (DFF_ / 128, M / 128);         // (24, 64)

    for (int l = 0; l < L_; l++) {
        size_t oDD = (size_t)l * D_ * D_;
        gemm_qkv<<<gQKV, 256, GS_SMEM_BYTES>>>(X, wq + oDD, wk + oDD, wv + oDD,
                                               bq + l * D_, bk + l * D_, bv + l * D_,
                                               Qb, Kb, Vb);
        attn_k<<<dim3(S_ / 64, H_, B_), 256>>>(Qb, Kb, Vb,
                                               rb + (size_t)l * (2 * S_ - 1) * H_, Cb);
        gemm_tc<0><<<gProj, 256, GS_SMEM_BYTES>>>(Cb, wo + oDD, bo + l * D_, Ab, D_, D_);
        ln_k<<<M, 256>>>(X, Ab, g1 + l * D_, be1 + l * D_, Y);
        gemm_tc<1><<<gF1, 256, GS_SMEM_BYTES>>>(Y, w1 + (size_t)l * D_ * DFF_, b1 + l * DFF_, Hb, DFF_, D_);
        gemm_tc<0><<<gProj, 256, GS_SMEM_BYTES>>>(Hb, w2 + (size_t)l * DFF_ * D_, b2 + l * D_, Ab, D_, DFF_);
        ln_k<<<M, 256>>>(Y, Ab, g2 + l * D_, be2 + l * D_, X);
    }

    pool_k<<<dim3(3, B_), 256>>>(X, Pp);
    gemm_k<1><<<dim3(6, 1), 256>>>(Pp, cw1, cb1, Ch, B_, D_ / 2, D_);
    gemm_k<0><<<dim3(2, 1), 256>>>(Ch, cw2, cb2, out, B_, NC_, D_ / 2);
}

// round 15
// speedup vs baseline: 3.9063x; 1.1244x over previous
#include <cuda_runtime.h>

// ---- problem constants ----
#define B_   16
#define S_   512
#define D_   768
#define H_   12
#define DK_  64
#define DFF_ 3072
#define L_   12
#define NC_  100

#define BSD  (B_*S_*D_)
#define BSF  (B_*S_*DFF_)
#define WDD  ((size_t)L_*D_*D_)      // 7,077,888
#define WDF  ((size_t)L_*D_*DFF_)    // 28,311,552

// X, Xr, Y, Yr, Qb, Kb, Vb, Cb, Ab (9xBSD) + Hb (BSF) + rounded weights + pooled
__device__ __align__(16) float g_scratch[9*(size_t)BSD + (size_t)BSF
                                         + 4*WDD + 2*WDF + B_*D_ + B_*(D_/2)];

__device__ __forceinline__ unsigned tf32u(float x) {
    unsigned u;
    asm("cvt.rna.tf32.f32 %0, %1;" : "=r"(u) : "f"(x));
    return u;
}
__device__ __forceinline__ float tf32f(float x) { return __uint_as_float(tf32u(x)); }

__device__ __forceinline__ void cpa16(void* dst, const void* src) {
    unsigned d = (unsigned)__cvta_generic_to_shared(dst);
    asm volatile("cp.async.cg.shared.global [%0], [%1], 16;\n" :: "r"(d), "l"(src));
}

#define CP_COMMIT() asm volatile("cp.async.commit_group;\n" ::: "memory")
#define CP_WAIT(n)  asm volatile("cp.async.wait_group %0;\n" :: "n"(n) : "memory")

#define MMA_TF32(d, a0,a1,a2,a3, b0,b1) \
    asm volatile("mma.sync.aligned.m16n8k8.row.col.f32.tf32.tf32.f32 " \
                 "{%0,%1,%2,%3}, {%4,%5,%6,%7}, {%8,%9}, {%0,%1,%2,%3};\n" \
      : "+f"((d)[0]), "+f"((d)[1]), "+f"((d)[2]), "+f"((d)[3]) \
      : "r"(a0), "r"(a1), "r"(a2), "r"(a3), "r"(b0), "r"(b1))

#define LDMX4(r0,r1,r2,r3, addr) \
    asm volatile("ldmatrix.sync.aligned.m8n8.x4.b16 {%0,%1,%2,%3}, [%4];" \
      : "=r"(r0), "=r"(r1), "=r"(r2), "=r"(r3) : "r"(addr))

// dynamic smem layout for the 3-stage BK=32 GEMM
#define GS_STAGES 3
#define AS_STRIDE 36    // 144B rows: 16B-aligned, ldmatrix phases conflict-free
#define BS_STRIDE 136   // 544B rows: frag LDS conflict-free
#define AS_ELEMS  (128 * AS_STRIDE)
#define BS_ELEMS  (32 * BS_STRIDE)
#define GS_SMEM_BYTES ((GS_STAGES * (AS_ELEMS + BS_ELEMS)) * sizeof(float))

// ---------------------------------------------------------------------------
// Weight pre-rounding to tf32 (rna), vectorized grid-stride
// ---------------------------------------------------------------------------
__global__ __launch_bounds__(256) void roundw_k(const float* __restrict__ s,
                                                float* __restrict__ d, int n4)
{
    for (int i = blockIdx.x * 256 + threadIdx.x; i < n4; i += gridDim.x * 256) {
        float4 v = ((const float4*)s)[i];
        v.x = tf32f(v.x); v.y = tf32f(v.y); v.z = tf32f(v.z); v.w = tf32f(v.w);
        ((float4*)d)[i] = v;
    }
}

// ---------------------------------------------------------------------------
// Embedding + sinusoidal positional encoding (writes full X and rounded Xr)
// ---------------------------------------------------------------------------
__global__ __launch_bounds__(256) void embed_k(const int* __restrict__ ids,
                                               const float* __restrict__ emb,
                                               float* __restrict__ X,
                                               float* __restrict__ Xr)
{
    int bs = blockIdx.x;
    int d  = blockIdx.y * 256 + threadIdx.x;
    int s  = bs & (S_ - 1);
    int tok = ids[bs];
    int i2 = (d >> 1) * 2;
    float freq = expf((float)i2 * (-9.210340371976184f / (float)D_));
    float ang  = (float)s * freq;
    float pe   = (d & 1) ? cosf(ang) : sinf(ang);
    float v = emb[(size_t)tok * D_ + d] + pe;
    X [(size_t)bs * D_ + d] = v;
    Xr[(size_t)bs * D_ + d] = tf32f(v);
}

// ---------------------------------------------------------------------------
// TF32 tensor-core GEMM core. A and W must be PRE-ROUNDED to tf32.
// 128x128 tile, BK=32, 3-stage cp.async, ldmatrix A-fragments, raw-bit B.
// ROUND=1 -> outputs written tf32-rounded (for GEMM-only consumers).
// ---------------------------------------------------------------------------
template<int ACT, int ROUND>
__device__ __forceinline__ void gemm_core(const float* __restrict__ A,
                                          const float* __restrict__ W,
                                          const float* __restrict__ bias,
                                          float* __restrict__ C,
                                          int N, int K, int m0, int n0)
{
    extern __shared__ __align__(16) float smem[];
    float* As = smem;                              // [st][128][AS_STRIDE]
    float* Bs = smem + GS_STAGES * AS_ELEMS;       // [st][32][BS_STRIDE]

    const int tid  = threadIdx.x;
    const int warp = tid >> 5, lane = tid & 31;
    const int wm   = (warp >> 2) * 64;
    const int wn   = (warp & 3) * 32;
    const int g    = lane >> 2;
    const int tg   = lane & 3;
    // ldmatrix lane->row/col mapping (x4: m0 rows0-7, m1 rows8-15, m2 cols+4, m3 both)
    const int lm_row = (lane & 7) + (lane & 8);
    const int lm_c4  = (lane & 16) ? 4 : 0;

    float acc[4][4][4];
    #pragma unroll
    for (int i = 0; i < 4; i++)
        #pragma unroll
        for (int j = 0; j < 4; j++)
            #pragma unroll
            for (int r = 0; r < 4; r++) acc[i][j][r] = 0.f;

    const int nk = K >> 5;

    auto load_stage = [&](int stage, int k0) {
        float* as = As + stage * AS_ELEMS;
        float* bs = Bs + stage * BS_ELEMS;
        #pragma unroll
        for (int i = 0; i < 4; i++) {
            int c = tid + i * 256;
            int ar = c >> 3, akc = (c & 7) * 4;
            cpa16(&as[ar * AS_STRIDE + akc], &A[(size_t)(m0 + ar) * K + k0 + akc]);
        }
        #pragma unroll
        for (int i = 0; i < 4; i++) {
            int c = tid + i * 256;
            int br = c >> 5, bnc = (c & 31) * 4;
            cpa16(&bs[br * BS_STRIDE + bnc], &W[(size_t)(k0 + br) * N + n0 + bnc]);
        }
        CP_COMMIT();
    };

    load_stage(0, 0);
    if (nk > 1) load_stage(1, 32);

    int st = 0;
    for (int it = 0; it < nk; it++) {
        CP_WAIT(1);
        __syncthreads();
        if (it + 2 < nk) load_stage((it + 2) % GS_STAGES, (it + 2) << 5);

        const float* as = As + st * AS_ELEMS;
        const float* bs = Bs + st * BS_ELEMS;
        const unsigned asb = (unsigned)__cvta_generic_to_shared(as);

        #pragma unroll
        for (int kk = 0; kk < 32; kk += 8) {
            unsigned a[4][4], b[4][2];
            #pragma unroll
            for (int mt = 0; mt < 4; mt++) {
                unsigned ad = asb + (unsigned)(((wm + mt * 16 + lm_row) * AS_STRIDE
                                               + kk + lm_c4) * 4);
                LDMX4(a[mt][0], a[mt][1], a[mt][2], a[mt][3], ad);
            }
            #pragma unroll
            for (int nt = 0; nt < 4; nt++) {
                int c = wn + nt * 8 + g;
                b[nt][0] = __float_as_uint(bs[(kk + tg    ) * BS_STRIDE + c]);
                b[nt][1] = __float_as_uint(bs[(kk + tg + 4) * BS_STRIDE + c]);
            }
            #pragma unroll
            for (int mt = 0; mt < 4; mt++)
                #pragma unroll
                for (int nt = 0; nt < 4; nt++)
                    MMA_TF32(acc[mt][nt], a[mt][0], a[mt][1], a[mt][2], a[mt][3],
                             b[nt][0], b[nt][1]);
        }
        st = (st + 1) % GS_STAGES;
    }

    #pragma unroll
    for (int mt = 0; mt < 4; mt++) {
        int r0 = m0 + wm + mt * 16 + g;
        #pragma unroll
        for (int nt = 0; nt < 4; nt++) {
            int cb = n0 + wn + nt * 8 + tg * 2;
            float b0 = bias[cb], b1 = bias[cb + 1];
            float v0 = acc[mt][nt][0] + b0;
            float v1 = acc[mt][nt][1] + b1;
            float v2 = acc[mt][nt][2] + b0;
            float v3 = acc[mt][nt][3] + b1;
            if (ACT) {
                v0 = fmaxf(v0, 0.f); v1 = fmaxf(v1, 0.f);
                v2 = fmaxf(v2, 0.f); v3 = fmaxf(v3, 0.f);
            }
            if (ROUND) {
                v0 = tf32f(v0); v1 = tf32f(v1);
                v2 = tf32f(v2); v3 = tf32f(v3);
            }
            *(float2*)&C[(size_t)r0 * N + cb]       = make_float2(v0, v1);
            *(float2*)&C[(size_t)(r0 + 8) * N + cb] = make_float2(v2, v3);
        }
    }
}

template<int ACT, int ROUND>
__global__ __launch_bounds__(256, 2) void gemm_tc(const float* __restrict__ A,
                                                  const float* __restrict__ W,
                                                  const float* __restrict__ bias,
                                                  float* __restrict__ C,
                                                  int N, int K)
{
    gemm_core<ACT, ROUND>(A, W, bias, C, N, K, blockIdx.y * 128, blockIdx.x * 128);
}

// Fused QKV (outputs rounded: they feed attention MMAs only)
__global__ __launch_bounds__(256, 2) void gemm_qkv(const float* __restrict__ X,
                                                   const float* __restrict__ wq,
                                                   const float* __restrict__ wk,
                                                   const float* __restrict__ wv,
                                                   const float* __restrict__ bq,
                                                   const float* __restrict__ bk,
                                                   const float* __restrict__ bv,
                                                   float* __restrict__ Qb,
                                                   float* __restrict__ Kb,
                                                   float* __restrict__ Vb)
{
    const int which = blockIdx.x / 6;
    const int n0 = (blockIdx.x % 6) * 128;
    const float* W  = (which == 0) ? wq : (which == 1) ? wk : wv;
    const float* bi = (which == 0) ? bq : (which == 1) ? bk : bv;
    float*       C  = (which == 0) ? Qb : (which == 1) ? Kb : Vb;
    gemm_core<0, 1>(X, W, bi, C, D_, D_, blockIdx.y * 128, n0);
}

// ---------------------------------------------------------------------------
// Small fp32 GEMM (classifier only)
// ---------------------------------------------------------------------------
template<int ACT>
__global__ __launch_bounds__(256) void gemm_k(const float* __restrict__ A,
                                              const float* __restrict__ W,
                                              const float* __restrict__ bias,
                                              float* __restrict__ C,
                                              int M, int N, int K)
{
    __shared__ float As[16][64];
    __shared__ float Ws[16][64];

    const int tid = threadIdx.x;
    const int m0 = blockIdx.y * 64, n0 = blockIdx.x * 64;
    const int ty = tid >> 4, tx = tid & 15;
    const int am = tid >> 2, ak = (tid & 3) * 4;
    const int wk = tid >> 4, wn = (tid & 15) * 4;

    float acc[4][4] = {};
    const bool aval = (m0 + am) < M;

    for (int k0 = 0; k0 < K; k0 += 16) {
        float4 av = make_float4(0.f, 0.f, 0.f, 0.f);
        if (aval) av = *(const float4*)&A[(size_t)(m0 + am) * K + k0 + ak];
        As[ak + 0][am] = av.x; As[ak + 1][am] = av.y;
        As[ak + 2][am] = av.z; As[ak + 3][am] = av.w;

        float4 wv;
        if (n0 + wn + 3 < N) {
            wv = *(const float4*)&W[(size_t)(k0 + wk) * N + n0 + wn];
        } else {
            const float* wr = &W[(size_t)(k0 + wk) * N];
            wv.x = (n0 + wn + 0 < N) ? wr[n0 + wn + 0] : 0.f;
            wv.y = (n0 + wn + 1 < N) ? wr[n0 + wn + 1] : 0.f;
            wv.z = (n0 + wn + 2 < N) ? wr[n0 + wn + 2] : 0.f;
            wv.w = 0.f;
        }
        Ws[wk][wn + 0] = wv.x; Ws[wk][wn + 1] = wv.y;
        Ws[wk][wn + 2] = wv.z; Ws[wk][wn + 3] = wv.w;

        __syncthreads();
        #pragma unroll
        for (int kk = 0; kk < 16; kk++) {
            float4 a = *(const float4*)&As[kk][ty * 4];
            float4 b = *(const float4*)&Ws[kk][tx * 4];
            acc[0][0] += a.x * b.x; acc[0][1] += a.x * b.y; acc[0][2] += a.x * b.z; acc[0][3] += a.x * b.w;
            acc[1][0] += a.y * b.x; acc[1][1] += a.y * b.y; acc[1][2] += a.y * b.z; acc[1][3] += a.y * b.w;
            acc[2][0] += a.z * b.x; acc[2][1] += a.z * b.y; acc[2][2] += a.z * b.z; acc[2][3] += a.z * b.w;
            acc[3][0] += a.w * b.x; acc[3][1] += a.w * b.y; acc[3][2] += a.w * b.z; acc[3][3] += a.w * b.w;
        }
        __syncthreads();
    }

    #pragma unroll
    for (int i = 0; i < 4; i++) {
        int m = m0 + ty * 4 + i;
        if (m >= M) continue;
        #pragma unroll
        for (int j = 0; j < 4; j++) {
            int n = n0 + tx * 4 + j;
            if (n < N) {
                float v = acc[i][j] + bias[n];
                if (ACT) v = fmaxf(v, 0.f);
                C[(size_t)m * N + n] = v;
            }
        }
    }
}

// ---------------------------------------------------------------------------
// Tensor-core flash attention. Q/K/V arrive tf32-pre-rounded (raw-bit loads);
// only softmax P still cvt'd. Output written tf32-rounded (feeds wo-GEMM only).
// ---------------------------------------------------------------------------
__global__ __launch_bounds__(256, 2) void attn_k(const float* __restrict__ Q,
                                                 const float* __restrict__ Km,
                                                 const float* __restrict__ V,
                                                 const float* __restrict__ rb,
                                                 float* __restrict__ O)
{
    __shared__ __align__(16) float QSs[64 * 68];
    __shared__ __align__(16) float Ks[32][68];
    __shared__ __align__(16) float Vs[32][72];
    __shared__ float m_s[64], l_s[64], al_s[64];
    __shared__ float rbias[96];

    float (*Ss)[36] = (float(*)[36])QSs;

    const int q0 = blockIdx.x * 64;
    const int h  = blockIdx.y;
    const int b  = blockIdx.z;

    const int tid  = threadIdx.x;
    const int warp = tid >> 5, lane = tid & 31;
    const int g    = lane >> 2, tg = lane & 3;
    const int wmS  = (warp >> 1) * 16, wnS = (warp & 1) * 16;
    const int wmP  = (warp >> 1) * 16, wnP = (warp & 1) * 32;

    #pragma unroll
    for (int r = 0; r < 4; r++) {
        int lin = tid + r * 256;
        int qr = lin >> 4, dc = (lin & 15) * 4;
        float4 v = *(const float4*)&Q[((size_t)(b * S_) + q0 + qr) * D_ + h * DK_ + dc];
        QSs[qr * 68 + dc + 0] = v.x; QSs[qr * 68 + dc + 1] = v.y;
        QSs[qr * 68 + dc + 2] = v.z; QSs[qr * 68 + dc + 3] = v.w;
    }
    if (tid < 64) { m_s[tid] = -1e30f; l_s[tid] = 0.f; }
    __syncthreads();

    unsigned qa[8][4];
    #pragma unroll
    for (int ks = 0; ks < 8; ks++) {
        int r = wmS + g;
        qa[ks][0] = __float_as_uint(QSs[(r    ) * 68 + ks * 8 + tg    ]);
        qa[ks][1] = __float_as_uint(QSs[(r + 8) * 68 + ks * 8 + tg    ]);
        qa[ks][2] = __float_as_uint(QSs[(r    ) * 68 + ks * 8 + tg + 4]);
        qa[ks][3] = __float_as_uint(QSs[(r + 8) * 68 + ks * 8 + tg + 4]);
    }

    float oacc[4][4];
    #pragma unroll
    for (int i = 0; i < 4; i++)
        #pragma unroll
        for (int j = 0; j < 4; j++) oacc[i][j] = 0.f;

    for (int j0 = 0; j0 < S_; j0 += 32) {
        __syncthreads();

        #pragma unroll
        for (int r = 0; r < 2; r++) {
            int lin = tid + r * 256;
            int kr = lin >> 4, dc = (lin & 15) * 4;
            size_t gi = ((size_t)(b * S_) + j0 + kr) * D_ + h * DK_ + dc;
            *(float4*)&Ks[kr][dc] = *(const float4*)&Km[gi];
            *(float4*)&Vs[kr][dc] = *(const float4*)&V[gi];
        }
        if (tid < 95) rbias[tid] = rb[(j0 - q0 + 448 + tid) * H_ + h];
        __syncthreads();

        float sc[2][4];
        #pragma unroll
        for (int nt = 0; nt < 2; nt++)
            #pragma unroll
            for (int r = 0; r < 4; r++) sc[nt][r] = 0.f;

        #pragma unroll
        for (int ks = 0; ks < 8; ks++) {
            unsigned kb[2][2];
            #pragma unroll
            for (int nt = 0; nt < 2; nt++) {
                int c = wnS + nt * 8 + g;
                kb[nt][0] = __float_as_uint(Ks[c][ks * 8 + tg    ]);
                kb[nt][1] = __float_as_uint(Ks[c][ks * 8 + tg + 4]);
            }
            #pragma unroll
            for (int nt = 0; nt < 2; nt++)
                MMA_TF32(sc[nt], qa[ks][0], qa[ks][1], qa[ks][2], qa[ks][3],
                         kb[nt][0], kb[nt][1]);
        }
        #pragma unroll
        for (int nt = 0; nt < 2; nt++) {
            int col = wnS + nt * 8 + tg * 2;
            int r0  = wmS + g;
            Ss[r0    ][col    ] = sc[nt][0] * 0.125f + rbias[63 + col - r0];
            Ss[r0    ][col + 1] = sc[nt][1] * 0.125f + rbias[64 + col - r0];
            Ss[r0 + 8][col    ] = sc[nt][2] * 0.125f + rbias[55 + col - r0];
            Ss[r0 + 8][col + 1] = sc[nt][3] * 0.125f + rbias[56 + col - r0];
        }
        __syncthreads();

        if (tid < 64) {
            float mo = m_s[tid], cm = mo;
            #pragma unroll
            for (int c = 0; c < 32; c++) cm = fmaxf(cm, Ss[tid][c]);
            float al = expf(mo - cm);
            float rs = 0.f;
            #pragma unroll
            for (int c = 0; c < 32; c++) {
                float p = expf(Ss[tid][c] - cm);
                Ss[tid][c] = p;
                rs += p;
            }
            l_s[tid] = l_s[tid] * al + rs;
            m_s[tid] = cm;
            al_s[tid] = al;
        }
        __syncthreads();

        float al0 = al_s[wmP + g], al1 = al_s[wmP + g + 8];
        #pragma unroll
        for (int nt = 0; nt < 4; nt++) {
            oacc[nt][0] *= al0; oacc[nt][1] *= al0;
            oacc[nt][2] *= al1; oacc[nt][3] *= al1;
        }
        #pragma unroll
        for (int ks = 0; ks < 4; ks++) {
            unsigned pa[4];
            int r = wmP + g;
            pa[0] = tf32u(Ss[r    ][ks * 8 + tg    ]);
            pa[1] = tf32u(Ss[r + 8][ks * 8 + tg    ]);
            pa[2] = tf32u(Ss[r    ][ks * 8 + tg + 4]);
            pa[3] = tf32u(Ss[r + 8][ks * 8 + tg + 4]);
            #pragma unroll
            for (int nt = 0; nt < 4; nt++) {
                unsigned vb0 = __float_as_uint(Vs[ks * 8 + tg    ][wnP + nt * 8 + g]);
                unsigned vb1 = __float_as_uint(Vs[ks * 8 + tg + 4][wnP + nt * 8 + g]);
                MMA_TF32(oacc[nt], pa[0], pa[1], pa[2], pa[3], vb0, vb1);
            }
        }
    }

    float inv0 = 1.f / l_s[wmP + g];
    float inv1 = 1.f / l_s[wmP + g + 8];
    #pragma unroll
    for (int nt = 0; nt < 4; nt++) {
        int col = wnP + nt * 8 + tg * 2;
        size_t o0 = ((size_t)(b * S_) + q0 + wmP + g    ) * D_ + h * DK_ + col;
        size_t o1 = ((size_t)(b * S_) + q0 + wmP + g + 8) * D_ + h * DK_ + col;
        *(float2*)&O[o0] = make_float2(tf32f(oacc[nt][0] * inv0), tf32f(oacc[nt][1] * inv0));
        *(float2*)&O[o1] = make_float2(tf32f(oacc[nt][2] * inv1), tf32f(oacc[nt][3] * inv1));
    }
}

// ---------------------------------------------------------------------------
// Fused residual-add + LayerNorm; writes full-precision Y and tf32-rounded Yr
// ---------------------------------------------------------------------------
__global__ __launch_bounds__(256) void ln_k(const float* __restrict__ X,
                                            const float* __restrict__ R,
                                            const float* __restrict__ g,
                                            const float* __restrict__ be,
                                            float* __restrict__ Y,
                                            float* __restrict__ Yr)
{
    __shared__ float ws1[8], ws2[8];
    const int row = blockIdx.x, tid = threadIdx.x;
    const int warp = tid >> 5, lane = tid & 31;
    const size_t off = (size_t)row * D_;

    float v0 = X[off + tid      ] + R[off + tid      ];
    float v1 = X[off + tid + 256] + R[off + tid + 256];
    float v2 = X[off + tid + 512] + R[off + tid + 512];

    float s = v0 + v1 + v2;
    #pragma unroll
    for (int o = 16; o > 0; o >>= 1) s += __shfl_xor_sync(0xffffffffu, s, o);
    if (lane == 0) ws1[warp] = s;
    __syncthreads();
    float mean = (ws1[0] + ws1[1] + ws1[2] + ws1[3] +
                  ws1[4] + ws1[5] + ws1[6] + ws1[7]) * (1.f / (float)D_);

    float d0 = v0 - mean, d1 = v1 - mean, d2 = v2 - mean;
    float q = d0 * d0 + d1 * d1 + d2 * d2;
    #pragma unroll
    for (int o = 16; o > 0; o >>= 1) q += __shfl_xor_sync(0xffffffffu, q, o);
    if (lane == 0) ws2[warp] = q;
    __syncthreads();
    float inv = rsqrtf((ws2[0] + ws2[1] + ws2[2] + ws2[3] +
                        ws2[4] + ws2[5] + ws2[6] + ws2[7]) * (1.f / (float)D_) + 1e-5f);

    float o0 = d0 * inv * g[tid      ] + be[tid      ];
    float o1 = d1 * inv * g[tid + 256] + be[tid + 256];
    float o2 = d2 * inv * g[tid + 512] + be[tid + 512];
    Y [off + tid      ] = o0;  Yr[off + tid      ] = tf32f(o0);
    Y [off + tid + 256] = o1;  Yr[off + tid + 256] = tf32f(o1);
    Y [off + tid + 512] = o2;  Yr[off + tid + 512] = tf32f(o2);
}

// ---------------------------------------------------------------------------
// Mean pooling over sequence
// ---------------------------------------------------------------------------
__global__ __launch_bounds__(256) void pool_k(const float* __restrict__ X,
                                              float* __restrict__ P)
{
    int b = blockIdx.y;
    int d = blockIdx.x * 256 + threadIdx.x;
    float s = 0.f;
    for (int sq = 0; sq < S_; sq++)
        s += X[(((size_t)b * S_) + sq) * D_ + d];
    P[(size_t)b * D_ + d] = s * (1.f / (float)S_);
}

// ---------------------------------------------------------------------------
extern "C" void kernel_launch(void* const* d_in, const int* in_sizes, int n_in,
                              void* d_out, int out_size)
{
    (void)in_sizes; (void)n_in; (void)out_size;

    const int*   ids = (const int*)  d_in[0];
    const float* emb = (const float*)d_in[1];
    const float* wq  = (const float*)d_in[2];
    const float* bq  = (const float*)d_in[3];
    const float* wk  = (const float*)d_in[4];
    const float* bk  = (const float*)d_in[5];
    const float* wv  = (const float*)d_in[6];
    const float* bv  = (const float*)d_in[7];
    const float* wo  = (const float*)d_in[8];
    const float* bo  = (const float*)d_in[9];
    const float* rb  = (const float*)d_in[10];
    const float* w1  = (const float*)d_in[11];
    const float* b1  = (const float*)d_in[12];
    const float* w2  = (const float*)d_in[13];
    const float* b2  = (const float*)d_in[14];
    const float* g1  = (const float*)d_in[15];
    const float* be1 = (const float*)d_in[16];
    const float* g2  = (const float*)d_in[17];
    const float* be2 = (const float*)d_in[18];
    const float* cw1 = (const float*)d_in[19];
    const float* cb1 = (const float*)d_in[20];
    const float* cw2 = (const float*)d_in[21];
    const float* cb2 = (const float*)d_in[22];
    float* out = (float*)d_out;

    float* base = nullptr;
    cudaGetSymbolAddress((void**)&base, g_scratch);

    float* X   = base;
    float* Xr  = base + 1 * (size_t)BSD;
    float* Y   = base + 2 * (size_t)BSD;
    float* Yr  = base + 3 * (size_t)BSD;
    float* Qb  = base + 4 * (size_t)BSD;
    float* Kb  = base + 5 * (size_t)BSD;
    float* Vb  = base + 6 * (size_t)BSD;
    float* Cb  = base + 7 * (size_t)BSD;
    float* Ab  = base + 8 * (size_t)BSD;
    float* Hb  = base + 9 * (size_t)BSD;
    float* wqR = Hb  + (size_t)BSF;
    float* wkR = wqR + WDD;
    float* wvR = wkR + WDD;
    float* woR = wvR + WDD;
    float* w1R = woR + WDD;
    float* w2R = w1R + WDF;
    float* Pp  = w2R + WDF;
    float* Ch  = Pp + B_ * D_;

    cudaFuncSetAttribute(gemm_tc<0,0>, cudaFuncAttributeMaxDynamicSharedMemorySize, (int)GS_SMEM_BYTES);
    cudaFuncSetAttribute(gemm_tc<1,1>, cudaFuncAttributeMaxDynamicSharedMemorySize, (int)GS_SMEM_BYTES);
    cudaFuncSetAttribute(gemm_qkv,     cudaFuncAttributeMaxDynamicSharedMemorySize, (int)GS_SMEM_BYTES);

    // pre-round all weights to tf32 (rna)
    roundw_k<<<2048, 256>>>(wq, wqR, (int)(WDD / 4));
    roundw_k<<<2048, 256>>>(wk, wkR, (int)(WDD / 4));
    roundw_k<<<2048, 256>>>(wv, wvR, (int)(WDD / 4));
    roundw_k<<<2048, 256>>>(wo, woR, (int)(WDD / 4));
    roundw_k<<<4096, 256>>>(w1, w1R, (int)(WDF / 4));
    roundw_k<<<4096, 256>>>(w2, w2R, (int)(WDF / 4));

    embed_k<<<dim3(B_ * S_, 3), 256>>>(ids, emb, X, Xr);

    const int M = B_ * S_;                   // 8192
    dim3 gProj(D_ / 128,  M / 128);          // (6, 64)
    dim3 gQKV (3 * D_ / 128, M / 128);       // (18, 64)
    dim3 gF1  (DFF_ / 128, M / 128);         // (24, 64)

    for (int l = 0; l < L_; l++) {
        size_t oDD = (size_t)l * D_ * D_;
        gemm_qkv<<<gQKV, 256, GS_SMEM_BYTES>>>(Xr, wqR + oDD, wkR + oDD, wvR + oDD,
                                               bq + l * D_, bk + l * D_, bv + l * D_,
                                               Qb, Kb, Vb);
        attn_k<<<dim3(S_ / 64, H_, B_), 256>>>(Qb, Kb, Vb,
                                               rb + (size_t)l * (2 * S_ - 1) * H_, Cb);
        gemm_tc<0,0><<<gProj, 256, GS_SMEM_BYTES>>>(Cb, woR + oDD, bo + l * D_, Ab, D_, D_);
        ln_k<<<M, 256>>>(X, Ab, g1 + l * D_, be1 + l * D_, Y, Yr);
        gemm_tc<1,1><<<gF1, 256, GS_SMEM_BYTES>>>(Yr, w1R + (size_t)l * D_ * DFF_,
                                                  b1 + l * DFF_, Hb, DFF_, D_);
        gemm_tc<0,0><<<gProj, 256, GS_SMEM_BYTES>>>(Hb, w2R + (size_t)l * DFF_ * D_,
                                                    b2 + l * D_, Ab, D_, DFF_);
        ln_k<<<M, 256>>>(Y, Ab, g2 + l * D_, be2 + l * D_, X, Xr);
    }

    pool_k<<<dim3(3, B_), 256>>>(X, Pp);
    gemm_k<1><<<dim3(6, 1), 256>>>(Pp, cw1, cb1, Ch, B_, D_ / 2, D_);
    gemm_k<0><<<dim3(2, 1), 256>>>(Ch, cw2, cb2, out, B_, NC_, D_ / 2);
}